// round 10
// baseline (speedup 1.0000x reference)
#include <cuda_runtime.h>
#include <cuda_bf16.h>
#include <cstdint>
#include <math.h>

#define Bn    4
#define SEQ   4096
#define Ein   2048
#define HD    2048
#define HEADS 16
#define DHd   128
#define MR    (Bn * SEQ)      // 16384
#define SPLITS 8

// ---------------------------------------------------------------------------
// PTX helpers (base-target safe: sm_80+ instructions only)
// ---------------------------------------------------------------------------
__device__ __forceinline__ uint32_t smem_u32(const void* p) {
    uint32_t a;
    asm("{ .reg .u64 t; cvta.to.shared.u64 t, %1; cvt.u32.u64 %0, t; }" : "=r"(a) : "l"(p));
    return a;
}

#define CP16(dst, src) \
    asm volatile("cp.async.cg.shared.global [%0], [%1], 16;" :: "r"(dst), "l"(src) : "memory")
#define CP_COMMIT() asm volatile("cp.async.commit_group;" ::: "memory")
#define CP_WAIT(n)  asm volatile("cp.async.wait_group %0;" :: "n"(n) : "memory")

#define LDMX4(r, addr) \
    asm volatile("ldmatrix.sync.aligned.m8n8.x4.shared.b16 {%0,%1,%2,%3}, [%4];" \
        : "=r"((r)[0]), "=r"((r)[1]), "=r"((r)[2]), "=r"((r)[3]) : "r"(addr))

#define MMA_BF16(d, a, b0v, b1v) \
    asm volatile("mma.sync.aligned.m16n8k16.row.col.f32.bf16.bf16.f32 " \
        "{%0,%1,%2,%3}, {%4,%5,%6,%7}, {%8,%9}, {%0,%1,%2,%3};" \
        : "+f"((d)[0]), "+f"((d)[1]), "+f"((d)[2]), "+f"((d)[3]) \
        : "r"((a)[0]), "r"((a)[1]), "r"((a)[2]), "r"((a)[3]), "r"(b0v), "r"(b1v))

// ---------------------------------------------------------------------------
// scratch (device globals; no allocation allowed)
// ---------------------------------------------------------------------------
__device__ float g_q [MR * HD];
__device__ float g_v [MR * HD];
__device__ float g_u [MR * HD];
__device__ float g_o [MR * HD];
__device__ float g_kv[SPLITS * Bn * HEADS * DHd * DHd];
__device__ float g_kvsum[Bn * HEADS * DHd * DHd];
__device__ __nv_bfloat16 g_xh [MR * Ein];
__device__ __nv_bfloat16 g_xl [MR * Ein];
__device__ __nv_bfloat16 g_lnh[MR * HD];
__device__ __nv_bfloat16 g_lnl[MR * HD];
__device__ __nv_bfloat16 g_wqkh[HD * Ein], g_wqkl[HD * Ein];   // [N][K] transposed
__device__ __nv_bfloat16 g_wvh [HD * Ein], g_wvl [HD * Ein];
__device__ __nv_bfloat16 g_wuh [HD * Ein], g_wul [HD * Ein];
__device__ __nv_bfloat16 g_woh [Ein * HD], g_wol [Ein * HD];

// ---------------------------------------------------------------------------
// batched bf16 3-product GEMM: for z in grid.z:
//   C[z] = act[z]( (Ah+Al) @ (Bh[z]+Bl[z])^T + bias[z] ),  dropping Al*Bl.
// BM=256 BN=128 BK=32, 3-stage ring, 8 warps (4m x 2n), warp tile 64x64.
// 1 CTA/SM, 144KB smem. mma:ldsm = 6:1 per warp-iter.
// ---------------------------------------------------------------------------
#define BM 256
#define BN 128
#define BK 32
#define STAGES 3
#define OFF_AH 0
#define OFF_AL 16384
#define OFF_BH 32768
#define OFF_BL 40960
#define STG_BYTES 49152
#define GEMM_SMEM (STAGES * STG_BYTES)           // 147456
#define NIT (2048 / BK)                          // 64

struct GemmBatch {
    const __nv_bfloat16* Bh[3];
    const __nv_bfloat16* Bl[3];
    const float* bias[3];
    float* C[3];
    int act[3];      // 0 none, 1 elu, 2 silu
};

__global__ void __launch_bounds__(256) gemm_bf16_3p(
    const __nv_bfloat16* __restrict__ Ah, const __nv_bfloat16* __restrict__ Al,
    GemmBatch P)
{
    extern __shared__ char smem[];
    const uint32_t sb = smem_u32(smem);
    const int tid = threadIdx.x;
    const int m0 = blockIdx.y * BM;
    const int n0 = blockIdx.x * BN;
    const int z  = blockIdx.z;
    const __nv_bfloat16* __restrict__ Bh = P.Bh[z];
    const __nv_bfloat16* __restrict__ Bl = P.Bl[z];

    const int lane = tid & 31, w = tid >> 5;
    const int wm = (w >> 1) * 64;        // 4 warps along m
    const int wn = (w & 1) * 64;         // 2 warps along n
    const int mi = lane >> 3, rowin = lane & 7;

    // A frag addressing (k16 x4 ldmatrix): mats {m0-7/k0-7, m8-15/k0-7, m0-7/k8-15, m8-15/k8-15}
    const int au = mi >> 1, aro = (mi & 1) << 3;
    uint32_t aoff[4]; int arx[4];
#pragma unroll
    for (int mt = 0; mt < 4; mt++) {
        int r = wm + mt * 16 + aro + rowin;
        aoff[mt] = r * 64;
        arx[mt] = (r >> 1) & 3;
    }
    // B frag addressing: mats {n0-7/k0-7, n0-7/k8-15, n8-15/k0-7, n8-15/k8-15}
    const int bu = mi & 1, bro = (mi >> 1) << 3;
    uint32_t boff[4]; int brx[4];
#pragma unroll
    for (int p = 0; p < 4; p++) {
        int r = wn + p * 16 + bro + rowin;
        boff[p] = OFF_BH + r * 64;
        brx[p] = (r >> 1) & 3;
    }

    // per-thread cp.async: A rows lr+{0,64,128,192}, B rows lr+{0,64}; chunk lu
    const int lr = tid >> 2, lu = tid & 3;
    const uint32_t swA = (uint32_t)(lr * 64 + ((lu ^ ((lr >> 1) & 3)) << 4));
    const __nv_bfloat16* Ahp = Ah + (size_t)(m0 + lr) * 2048 + lu * 8;
    const __nv_bfloat16* Alp = Al + (size_t)(m0 + lr) * 2048 + lu * 8;
    const __nv_bfloat16* Bhp = Bh + (size_t)(n0 + lr) * 2048 + lu * 8;
    const __nv_bfloat16* Blp = Bl + (size_t)(n0 + lr) * 2048 + lu * 8;

    float acc[4][8][4] = {};

    // -------- prologue: prefetch stages 0,1 --------
#pragma unroll
    for (int s = 0; s < STAGES - 1; s++) {
        const uint32_t st = sb + s * STG_BYTES;
        const int k0 = s * BK;
#pragma unroll
        for (int i = 0; i < 4; i++) {
            CP16(st + OFF_AH + swA + i * 4096, Ahp + k0 + (size_t)(i * 64) * 2048);
            CP16(st + OFF_AL + swA + i * 4096, Alp + k0 + (size_t)(i * 64) * 2048);
        }
#pragma unroll
        for (int i = 0; i < 2; i++) {
            CP16(st + OFF_BH + swA + i * 4096, Bhp + k0 + (size_t)(i * 64) * 2048);
            CP16(st + OFF_BL + swA + i * 4096, Blp + k0 + (size_t)(i * 64) * 2048);
        }
        CP_COMMIT();
    }

    int cs = 0, ls = STAGES - 1;
    for (int it = 0; it < NIT; it++) {
        CP_WAIT(STAGES - 2);
        __syncthreads();

        // issue next-stage loads first (overlap with MMA block)
        const int nx = it + STAGES - 1;
        if (nx < NIT) {
            const uint32_t st2 = sb + ls * STG_BYTES;
            const int k0 = nx * BK;
#pragma unroll
            for (int i = 0; i < 4; i++) {
                CP16(st2 + OFF_AH + swA + i * 4096, Ahp + k0 + (size_t)(i * 64) * 2048);
                CP16(st2 + OFF_AL + swA + i * 4096, Alp + k0 + (size_t)(i * 64) * 2048);
            }
#pragma unroll
            for (int i = 0; i < 2; i++) {
                CP16(st2 + OFF_BH + swA + i * 4096, Bhp + k0 + (size_t)(i * 64) * 2048);
                CP16(st2 + OFF_BL + swA + i * 4096, Blp + k0 + (size_t)(i * 64) * 2048);
            }
            CP_COMMIT();
        }

        const uint32_t st = sb + cs * STG_BYTES;
#pragma unroll
        for (int ks = 0; ks < 2; ks++) {
            uint32_t ah[4][4];
#pragma unroll
            for (int mt = 0; mt < 4; mt++)
                LDMX4(ah[mt], st + OFF_AH + aoff[mt] + (uint32_t)(((2 * ks + au) ^ arx[mt]) << 4));
            uint32_t bb[4][4];
#pragma unroll
            for (int p = 0; p < 4; p++)
                LDMX4(bb[p], st + boff[p] + (uint32_t)(((2 * ks + bu) ^ brx[p]) << 4));
            // Ah * Bh
#pragma unroll
            for (int mt = 0; mt < 4; mt++)
#pragma unroll
                for (int nt = 0; nt < 8; nt++)
                    MMA_BF16(acc[mt][nt], ah[mt], bb[nt >> 1][(nt & 1) * 2], bb[nt >> 1][(nt & 1) * 2 + 1]);
            // Al * Bh
            {
                uint32_t al[4][4];
#pragma unroll
                for (int mt = 0; mt < 4; mt++)
                    LDMX4(al[mt], st + OFF_AL + aoff[mt] + (uint32_t)(((2 * ks + au) ^ arx[mt]) << 4));
#pragma unroll
                for (int mt = 0; mt < 4; mt++)
#pragma unroll
                    for (int nt = 0; nt < 8; nt++)
                        MMA_BF16(acc[mt][nt], al[mt], bb[nt >> 1][(nt & 1) * 2], bb[nt >> 1][(nt & 1) * 2 + 1]);
            }
            // Ah * Bl (reuse bb regs)
#pragma unroll
            for (int p = 0; p < 4; p++)
                LDMX4(bb[p], st + boff[p] + 8192u + (uint32_t)(((2 * ks + bu) ^ brx[p]) << 4));
#pragma unroll
            for (int mt = 0; mt < 4; mt++)
#pragma unroll
                for (int nt = 0; nt < 8; nt++)
                    MMA_BF16(acc[mt][nt], ah[mt], bb[nt >> 1][(nt & 1) * 2], bb[nt >> 1][(nt & 1) * 2 + 1]);
        }
        if (++cs == STAGES) cs = 0;
        if (++ls == STAGES) ls = 0;
    }

    // -------- epilogue --------
    const float* __restrict__ bias = P.bias[z];
    float* __restrict__ C = P.C[z];
    const int act = P.act[z];
    const int g = lane >> 2, t = lane & 3;
#pragma unroll
    for (int mt = 0; mt < 4; mt++) {
#pragma unroll
        for (int nt = 0; nt < 8; nt++) {
            const int rm = m0 + wm + mt * 16 + g;
            const int cn = n0 + wn + nt * 8 + 2 * t;
            const float b0 = bias[cn], b1 = bias[cn + 1];
            float v0 = acc[mt][nt][0] + b0;
            float v1 = acc[mt][nt][1] + b1;
            float v2 = acc[mt][nt][2] + b0;
            float v3 = acc[mt][nt][3] + b1;
            if (act == 1) {
                v0 = v0 > 0.f ? v0 : (expf(v0) - 1.f);
                v1 = v1 > 0.f ? v1 : (expf(v1) - 1.f);
                v2 = v2 > 0.f ? v2 : (expf(v2) - 1.f);
                v3 = v3 > 0.f ? v3 : (expf(v3) - 1.f);
            } else if (act == 2) {
                v0 = v0 / (1.f + expf(-v0));
                v1 = v1 / (1.f + expf(-v1));
                v2 = v2 / (1.f + expf(-v2));
                v3 = v3 / (1.f + expf(-v3));
            }
            *(float2*)(C + (size_t)rm * 2048 + cn) = make_float2(v0, v1);
            *(float2*)(C + (size_t)(rm + 8) * 2048 + cn) = make_float2(v2, v3);
        }
    }
}

// ---------------------------------------------------------------------------
// prep kernels
// ---------------------------------------------------------------------------
__global__ void split_kernel(const float* __restrict__ x,
                             __nv_bfloat16* __restrict__ h, __nv_bfloat16* __restrict__ l, int n4) {
    int i = blockIdx.x * blockDim.x + threadIdx.x;
    if (i >= n4) return;
    float4 v = ((const float4*)x)[i];
    __nv_bfloat16 h0 = __float2bfloat16(v.x), h1 = __float2bfloat16(v.y);
    __nv_bfloat16 h2 = __float2bfloat16(v.z), h3 = __float2bfloat16(v.w);
    __nv_bfloat162* hp = (__nv_bfloat162*)h;
    __nv_bfloat162* lp = (__nv_bfloat162*)l;
    hp[i * 2 + 0] = __nv_bfloat162(h0, h1);
    hp[i * 2 + 1] = __nv_bfloat162(h2, h3);
    lp[i * 2 + 0] = __nv_bfloat162(__float2bfloat16(v.x - __bfloat162float(h0)),
                                   __float2bfloat16(v.y - __bfloat162float(h1)));
    lp[i * 2 + 1] = __nv_bfloat162(__float2bfloat16(v.z - __bfloat162float(h2)),
                                   __float2bfloat16(v.w - __bfloat162float(h3)));
}

// 4 weight matrices W[K,N] fp32 -> T[N,K] bf16 hi/lo, one launch (grid.z selects W)
struct TsplitBatch {
    const float* W[4];
    __nv_bfloat16* Th[4];
    __nv_bfloat16* Tl[4];
};
__global__ void tsplit_kernel(TsplitBatch P) {
    __shared__ float tile[32][33];
    const float* __restrict__ W = P.W[blockIdx.z];
    __nv_bfloat16* __restrict__ Th = P.Th[blockIdx.z];
    __nv_bfloat16* __restrict__ Tl = P.Tl[blockIdx.z];
    const int k0 = blockIdx.y * 32, n0 = blockIdx.x * 32;
    const int tx = threadIdx.x, ty = threadIdx.y;
#pragma unroll
    for (int i = 0; i < 32; i += 8)
        tile[ty + i][tx] = W[(size_t)(k0 + ty + i) * 2048 + n0 + tx];
    __syncthreads();
#pragma unroll
    for (int i = 0; i < 32; i += 8) {
        float v = tile[tx][ty + i];
        __nv_bfloat16 hv = __float2bfloat16(v);
        size_t o = (size_t)(n0 + ty + i) * 2048 + k0 + tx;
        Th[o] = hv;
        Tl[o] = __float2bfloat16(v - __bfloat162float(hv));
    }
}

// ---------------------------------------------------------------------------
// kv = q^T v per (b,h), split over sequence (fp32 SIMT)
// ---------------------------------------------------------------------------
__global__ void kv_kernel() {
    __shared__ float qs[16][128];
    __shared__ float vs[16][128];
    const int bh = blockIdx.x;
    const int b = bh / HEADS, h = bh % HEADS;
    const int split = blockIdx.y;
    const int chunk = SEQ / SPLITS;          // 512
    const int n0 = split * chunk;
    const int tid = threadIdx.x;
    const int tx = tid & 15, ty = tid >> 4;
    const size_t base = (size_t)(b * SEQ) * HD + h * DHd;

    float acc[8][8] = {};
    for (int nt = 0; nt < chunk; nt += 16) {
#pragma unroll
        for (int l = 0; l < 2; l++) {
            const int idx = tid + l * 256;
            const int r = idx >> 5;
            const int c = (idx & 31) * 4;
            const size_t off = base + (size_t)(n0 + nt + r) * HD + c;
            *(float4*)&qs[r][c] = *(const float4*)(g_q + off);
            *(float4*)&vs[r][c] = *(const float4*)(g_v + off);
        }
        __syncthreads();
#pragma unroll
        for (int kk = 0; kk < 16; kk++) {
            float rq[8], rv[8];
#pragma unroll
            for (int i = 0; i < 8; i++) rq[i] = qs[kk][ty * 8 + i];
#pragma unroll
            for (int j = 0; j < 8; j++) rv[j] = vs[kk][tx * 8 + j];
#pragma unroll
            for (int i = 0; i < 8; i++)
#pragma unroll
                for (int j = 0; j < 8; j++)
                    acc[i][j] += rq[i] * rv[j];
        }
        __syncthreads();
    }
    float* kvp = g_kv + ((size_t)split * Bn * HEADS + bh) * DHd * DHd;
#pragma unroll
    for (int i = 0; i < 8; i++)
#pragma unroll
        for (int j = 0; j < 8; j++)
            kvp[(ty * 8 + i) * DHd + tx * 8 + j] = acc[i][j];
}

// ---------------------------------------------------------------------------
// reduce SPLITS kv slices -> g_kvsum
// ---------------------------------------------------------------------------
__global__ void kvsum_kernel() {
    const int n4 = Bn * HEADS * DHd * DHd / 4;
    const size_t stride4 = (size_t)Bn * HEADS * DHd * DHd / 4;
    int i = blockIdx.x * blockDim.x + threadIdx.x;
    if (i >= n4) return;
    const float4* src = (const float4*)g_kv;
    float4 s = src[i];
#pragma unroll
    for (int sp = 1; sp < SPLITS; sp++) {
        float4 t = src[i + sp * stride4];
        s.x += t.x; s.y += t.y; s.z += t.z; s.w += t.w;
    }
    ((float4*)g_kvsum)[i] = s;
}

// ---------------------------------------------------------------------------
// out = q @ kvsum per (b,h) (fp32 SIMT)
// ---------------------------------------------------------------------------
__global__ void out_kernel() {
    __shared__ float As[16][64];
    __shared__ float Bs[16][128];
    const int m0 = blockIdx.x * 64;
    const int h = blockIdx.y;
    const int b = m0 / SEQ;
    const int tid = threadIdx.x;
    const int tx = tid & 15, ty = tid >> 4;
    const size_t kvoff = (size_t)(b * HEADS + h) * DHd * DHd;

    float acc[4][8] = {};
    const int a_r = tid >> 2;
    const int a_s = (tid & 3) * 4;

    for (int k0 = 0; k0 < DHd; k0 += 16) {
        float4 av = *(const float4*)(g_q + (size_t)(m0 + a_r) * HD + h * DHd + k0 + a_s);
        As[a_s + 0][a_r] = av.x;
        As[a_s + 1][a_r] = av.y;
        As[a_s + 2][a_r] = av.z;
        As[a_s + 3][a_r] = av.w;
#pragma unroll
        for (int l = 0; l < 2; l++) {
            const int idx = tid + l * 256;
            const int r = idx >> 5;
            const int c = (idx & 31) * 4;
            *(float4*)&Bs[r][c] = *(const float4*)(g_kvsum + kvoff + (size_t)(k0 + r) * DHd + c);
        }
        __syncthreads();
#pragma unroll
        for (int kk = 0; kk < 16; kk++) {
            float ra[4], rb[8];
#pragma unroll
            for (int i = 0; i < 4; i++) ra[i] = As[kk][ty * 4 + i];
#pragma unroll
            for (int j = 0; j < 8; j++) rb[j] = Bs[kk][tx * 8 + j];
#pragma unroll
            for (int i = 0; i < 4; i++)
#pragma unroll
                for (int j = 0; j < 8; j++)
                    acc[i][j] += ra[i] * rb[j];
        }
        __syncthreads();
    }
#pragma unroll
    for (int i = 0; i < 4; i++)
#pragma unroll
        for (int j = 0; j < 8; j++)
            g_o[(size_t)(m0 + ty * 4 + i) * HD + h * DHd + tx * 8 + j] = acc[i][j];
}

// ---------------------------------------------------------------------------
// LayerNorm over HD, * gate u, emit bf16 hi/lo for final GEMM
// ---------------------------------------------------------------------------
__global__ void ln_mul_kernel(const float* __restrict__ lng, const float* __restrict__ lnb) {
    __shared__ float buf[HD];
    __shared__ float red[256];
    const int row = blockIdx.x;
    const int tid = threadIdx.x;
    const float* orow = g_o + (size_t)row * HD;
    const float* urow = g_u + (size_t)row * HD;

    float s = 0.f;
    for (int c = tid; c < HD; c += 256) { float v = orow[c]; buf[c] = v; s += v; }
    red[tid] = s; __syncthreads();
    for (int off = 128; off; off >>= 1) { if (tid < off) red[tid] += red[tid + off]; __syncthreads(); }
    const float mean = red[0] * (1.f / HD);
    __syncthreads();

    float s2 = 0.f;
    for (int c = tid; c < HD; c += 256) { float d = buf[c] - mean; s2 += d * d; }
    red[tid] = s2; __syncthreads();
    for (int off = 128; off; off >>= 1) { if (tid < off) red[tid] += red[tid + off]; __syncthreads(); }
    const float rstd = rsqrtf(red[0] * (1.f / HD) + 1e-5f);

    for (int c = tid; c < HD; c += 256) {
        float v = ((buf[c] - mean) * rstd * lng[c] + lnb[c]) * urow[c];
        __nv_bfloat16 hv = __float2bfloat16(v);
        g_lnh[(size_t)row * HD + c] = hv;
        g_lnl[(size_t)row * HD + c] = __float2bfloat16(v - __bfloat162float(hv));
    }
}

// ---------------------------------------------------------------------------
// launch
// ---------------------------------------------------------------------------
extern "C" void kernel_launch(void* const* d_in, const int* in_sizes, int n_in,
                              void* d_out, int out_size) {
    const float* x   = (const float*)d_in[0];
    const float* Wqk = (const float*)d_in[1];
    const float* bqk = (const float*)d_in[2];
    const float* Wv  = (const float*)d_in[3];
    const float* bv  = (const float*)d_in[4];
    const float* Wu  = (const float*)d_in[5];
    const float* bu  = (const float*)d_in[6];
    const float* Wo  = (const float*)d_in[7];
    const float* bo  = (const float*)d_in[8];
    const float* lng = (const float*)d_in[9];
    const float* lnb = (const float*)d_in[10];
    float* out = (float*)d_out;

    float *pq, *pv, *pu;
    __nv_bfloat16 *pxh, *pxl, *plnh, *plnl;
    __nv_bfloat16 *pwqkh, *pwqkl, *pwvh, *pwvl, *pwuh, *pwul, *pwoh, *pwol;
    cudaGetSymbolAddress((void**)&pq, g_q);
    cudaGetSymbolAddress((void**)&pv, g_v);
    cudaGetSymbolAddress((void**)&pu, g_u);
    cudaGetSymbolAddress((void**)&pxh, g_xh);
    cudaGetSymbolAddress((void**)&pxl, g_xl);
    cudaGetSymbolAddress((void**)&plnh, g_lnh);
    cudaGetSymbolAddress((void**)&plnl, g_lnl);
    cudaGetSymbolAddress((void**)&pwqkh, g_wqkh);
    cudaGetSymbolAddress((void**)&pwqkl, g_wqkl);
    cudaGetSymbolAddress((void**)&pwvh, g_wvh);
    cudaGetSymbolAddress((void**)&pwvl, g_wvl);
    cudaGetSymbolAddress((void**)&pwuh, g_wuh);
    cudaGetSymbolAddress((void**)&pwul, g_wul);
    cudaGetSymbolAddress((void**)&pwoh, g_woh);
    cudaGetSymbolAddress((void**)&pwol, g_wol);

    cudaFuncSetAttribute(gemm_bf16_3p, cudaFuncAttributeMaxDynamicSharedMemorySize, GEMM_SMEM);

    // prep: split x; transpose+split 4 weights in one launch
    {
        int n4 = MR * Ein / 4;
        split_kernel<<<(n4 + 255) / 256, 256>>>(x, pxh, pxl, n4);
        TsplitBatch T;
        T.W[0] = Wqk; T.Th[0] = pwqkh; T.Tl[0] = pwqkl;
        T.W[1] = Wv;  T.Th[1] = pwvh;  T.Tl[1] = pwvl;
        T.W[2] = Wu;  T.Th[2] = pwuh;  T.Tl[2] = pwul;
        T.W[3] = Wo;  T.Th[3] = pwoh;  T.Tl[3] = pwol;
        tsplit_kernel<<<dim3(64, 64, 4), dim3(32, 8)>>>(T);
    }

    // merged q/v/u GEMM: z=0 q(elu), z=1 v(silu), z=2 u(silu)
    {
        GemmBatch P;
        P.Bh[0] = pwqkh; P.Bl[0] = pwqkl; P.bias[0] = bqk; P.C[0] = pq; P.act[0] = 1;
        P.Bh[1] = pwvh;  P.Bl[1] = pwvl;  P.bias[1] = bv;  P.C[1] = pv; P.act[1] = 2;
        P.Bh[2] = pwuh;  P.Bl[2] = pwul;  P.bias[2] = bu;  P.C[2] = pu; P.act[2] = 2;
        dim3 g3(HD / BN, MR / BM, 3);     // (16, 64, 3)
        gemm_bf16_3p<<<g3, 256, GEMM_SMEM>>>(pxh, pxl, P);
    }

    // linear attention
    kv_kernel<<<dim3(Bn * HEADS, SPLITS), 256>>>();
    kvsum_kernel<<<(Bn * HEADS * DHd * DHd / 4 + 255) / 256, 256>>>();
    out_kernel<<<dim3(MR / 64, HEADS), 256>>>();

    // LN * gate -> bf16 hi/lo
    ln_mul_kernel<<<MR, 256>>>(lng, lnb);

    // y = ln_out @ Wo + bo
    {
        GemmBatch P;
        P.Bh[0] = pwoh; P.Bl[0] = pwol; P.bias[0] = bo; P.C[0] = out; P.act[0] = 0;
        dim3 g1(HD / BN, MR / BM, 1);
        gemm_bf16_3p<<<g1, 256, GEMM_SMEM>>>(plnh, plnl, P);
    }
}

// round 11
// speedup vs baseline: 2.2224x; 2.2224x over previous
#include <cuda_runtime.h>
#include <cuda_fp16.h>
#include <cstdint>
#include <math.h>

#define Bn    4
#define SEQ   4096
#define Ein   2048
#define HD    2048
#define HEADS 16
#define DHd   128
#define MR    (Bn * SEQ)      // 16384
#define SPLITS 4

// ---------------------------------------------------------------------------
// PTX helpers (base-target safe: sm_80+ instructions only)
// ---------------------------------------------------------------------------
__device__ __forceinline__ uint32_t smem_u32(const void* p) {
    uint32_t a;
    asm("{ .reg .u64 t; cvta.to.shared.u64 t, %1; cvt.u32.u64 %0, t; }" : "=r"(a) : "l"(p));
    return a;
}

#define CP16(dst, src) \
    asm volatile("cp.async.cg.shared.global [%0], [%1], 16;" :: "r"(dst), "l"(src) : "memory")
#define CP_COMMIT() asm volatile("cp.async.commit_group;" ::: "memory")
#define CP_WAIT(n)  asm volatile("cp.async.wait_group %0;" :: "n"(n) : "memory")

#define LDMX4(r, addr) \
    asm volatile("ldmatrix.sync.aligned.m8n8.x4.shared.b16 {%0,%1,%2,%3}, [%4];" \
        : "=r"((r)[0]), "=r"((r)[1]), "=r"((r)[2]), "=r"((r)[3]) : "r"(addr))

#define MMA_F16(d, a, b0v, b1v) \
    asm volatile("mma.sync.aligned.m16n8k16.row.col.f32.f16.f16.f32 " \
        "{%0,%1,%2,%3}, {%4,%5,%6,%7}, {%8,%9}, {%0,%1,%2,%3};" \
        : "+f"((d)[0]), "+f"((d)[1]), "+f"((d)[2]), "+f"((d)[3]) \
        : "r"((a)[0]), "r"((a)[1]), "r"((a)[2]), "r"((a)[3]), "r"(b0v), "r"(b1v))

// ---------------------------------------------------------------------------
// scratch (device globals; no allocation allowed)
// ---------------------------------------------------------------------------
__device__ float g_q [MR * HD];
__device__ float g_v [MR * HD];
__device__ float g_u [MR * HD];
__device__ float g_o [MR * HD];
__device__ float g_kv[SPLITS * Bn * HEADS * DHd * DHd];
__device__ float g_kvsum[Bn * HEADS * DHd * DHd];
__device__ __half g_xh [MR * Ein];         // x hi
__device__ __half g_xl [MR * Ein];         // x lo
__device__ __half g_lnh[MR * HD];
__device__ __half g_lnl[MR * HD];
__device__ __half g_wqk[HD * Ein];         // [N][K] transposed, single fp16
__device__ __half g_wv [HD * Ein];
__device__ __half g_wu [HD * Ein];
__device__ __half g_wo [Ein * HD];

// ---------------------------------------------------------------------------
// batched fp16 2-product GEMM: C[z] = act[z]( (Ah+Al) @ B[z]^T + bias[z] )
// A = fp16 hi/lo pair (error ~2^-22), B = single fp16 (random rounding 2^-11).
// BM=128 BN=128 BK=32, 3-stage cp.async ring, 8 warps (2m x 4n), warp 64x32.
// Stage = 24KB (Ah|Al|B of 8KB), 72KB smem -> 2 CTAs/SM.
// ---------------------------------------------------------------------------
#define BM 128
#define BN 128
#define BK 32
#define STAGES 3
#define OFF_AH 0
#define OFF_AL 8192
#define OFF_B  16384
#define STG_BYTES 24576
#define GEMM_SMEM (STAGES * STG_BYTES)           // 73728
#define NIT (2048 / BK)                          // 64

struct GemmBatch {
    const __half* B[3];
    const float* bias[3];
    float* C[3];
    int act[3];      // 0 none, 1 elu, 2 silu
};

__global__ void __launch_bounds__(256, 2) gemm_f16_2p(
    const __half* __restrict__ Ah, const __half* __restrict__ Al,
    GemmBatch P)
{
    extern __shared__ char smem[];
    const uint32_t sb = smem_u32(smem);
    const int tid = threadIdx.x;
    const int m0 = blockIdx.y * BM;
    const int n0 = blockIdx.x * BN;
    const int z  = blockIdx.z;
    const __half* __restrict__ Bp0 = P.B[z];

    const int lane = tid & 31, w = tid >> 5;
    const int wm = (w >> 2) * 64;        // warp m offset
    const int wn = (w & 3) * 32;         // warp n offset
    const int mi = lane >> 3, rowin = lane & 7;

    const int au = mi >> 1, aro = (mi & 1) << 3;
    uint32_t aoff[4]; int arx[4];
#pragma unroll
    for (int mt = 0; mt < 4; mt++) {
        int r = wm + mt * 16 + aro + rowin;
        aoff[mt] = r * 64;
        arx[mt] = (r >> 1) & 3;
    }
    const int bu = mi & 1, bro = (mi >> 1) << 3;
    uint32_t boff[2]; int brx[2];
#pragma unroll
    for (int p = 0; p < 2; p++) {
        int r = wn + p * 16 + bro + rowin;
        boff[p] = OFF_B + r * 64;
        brx[p] = (r >> 1) & 3;
    }

    // per-thread cp.async indices: rows lr, lr+64; 16B chunk lu
    const int lr = tid >> 2, lu = tid & 3;
    const uint32_t sw0 = (uint32_t)(lr * 64 + ((lu ^ ((lr >> 1) & 3)) << 4));
    const __half* Ahp = Ah + (size_t)(m0 + lr) * 2048 + lu * 8;
    const __half* Alp = Al + (size_t)(m0 + lr) * 2048 + lu * 8;
    const __half* Bpp = Bp0 + (size_t)(n0 + lr) * 2048 + lu * 8;

    float acc[4][4][4] = {};

    // -------- prologue: prefetch stages 0,1 --------
#pragma unroll
    for (int s = 0; s < STAGES - 1; s++) {
        const uint32_t st = sb + s * STG_BYTES;
        const int k0 = s * BK;
        CP16(st + OFF_AH + sw0,        Ahp + k0);
        CP16(st + OFF_AH + sw0 + 4096, Ahp + k0 + (size_t)64 * 2048);
        CP16(st + OFF_AL + sw0,        Alp + k0);
        CP16(st + OFF_AL + sw0 + 4096, Alp + k0 + (size_t)64 * 2048);
        CP16(st + OFF_B  + sw0,        Bpp + k0);
        CP16(st + OFF_B  + sw0 + 4096, Bpp + k0 + (size_t)64 * 2048);
        CP_COMMIT();
    }

    int cs = 0, ls = STAGES - 1;
    for (int it = 0; it < NIT; it++) {
        CP_WAIT(STAGES - 2);
        __syncthreads();

        // next-stage loads first (overlap with MMA block)
        const int nx = it + STAGES - 1;
        if (nx < NIT) {
            const uint32_t st2 = sb + ls * STG_BYTES;
            const int k0 = nx * BK;
            CP16(st2 + OFF_AH + sw0,        Ahp + k0);
            CP16(st2 + OFF_AH + sw0 + 4096, Ahp + k0 + (size_t)64 * 2048);
            CP16(st2 + OFF_AL + sw0,        Alp + k0);
            CP16(st2 + OFF_AL + sw0 + 4096, Alp + k0 + (size_t)64 * 2048);
            CP16(st2 + OFF_B  + sw0,        Bpp + k0);
            CP16(st2 + OFF_B  + sw0 + 4096, Bpp + k0 + (size_t)64 * 2048);
            CP_COMMIT();
        }

        const uint32_t st = sb + cs * STG_BYTES;
#pragma unroll
        for (int ks = 0; ks < 2; ks++) {
            uint32_t bb[2][4];
#pragma unroll
            for (int p = 0; p < 2; p++)
                LDMX4(bb[p], st + boff[p] + (uint32_t)(((2 * ks + bu) ^ brx[p]) << 4));
            uint32_t ah[4][4];
#pragma unroll
            for (int mt = 0; mt < 4; mt++)
                LDMX4(ah[mt], st + OFF_AH + aoff[mt] + (uint32_t)(((2 * ks + au) ^ arx[mt]) << 4));
            // Ah * B
#pragma unroll
            for (int mt = 0; mt < 4; mt++)
#pragma unroll
                for (int nt = 0; nt < 4; nt++)
                    MMA_F16(acc[mt][nt], ah[mt], bb[nt >> 1][(nt & 1) * 2], bb[nt >> 1][(nt & 1) * 2 + 1]);
            // Al * B (reuse ah regs)
#pragma unroll
            for (int mt = 0; mt < 4; mt++)
                LDMX4(ah[mt], st + OFF_AL + aoff[mt] + (uint32_t)(((2 * ks + au) ^ arx[mt]) << 4));
#pragma unroll
            for (int mt = 0; mt < 4; mt++)
#pragma unroll
                for (int nt = 0; nt < 4; nt++)
                    MMA_F16(acc[mt][nt], ah[mt], bb[nt >> 1][(nt & 1) * 2], bb[nt >> 1][(nt & 1) * 2 + 1]);
        }
        if (++cs == STAGES) cs = 0;
        if (++ls == STAGES) ls = 0;
    }

    // -------- epilogue --------
    const float* __restrict__ bias = P.bias[z];
    float* __restrict__ C = P.C[z];
    const int act = P.act[z];
    const int g = lane >> 2, t = lane & 3;
#pragma unroll
    for (int mt = 0; mt < 4; mt++) {
#pragma unroll
        for (int nt = 0; nt < 4; nt++) {
            const int rm = m0 + wm + mt * 16 + g;
            const int cn = n0 + wn + nt * 8 + 2 * t;
            const float b0 = bias[cn], b1 = bias[cn + 1];
            float v0 = acc[mt][nt][0] + b0;
            float v1 = acc[mt][nt][1] + b1;
            float v2 = acc[mt][nt][2] + b0;
            float v3 = acc[mt][nt][3] + b1;
            if (act == 1) {
                v0 = v0 > 0.f ? v0 : (expf(v0) - 1.f);
                v1 = v1 > 0.f ? v1 : (expf(v1) - 1.f);
                v2 = v2 > 0.f ? v2 : (expf(v2) - 1.f);
                v3 = v3 > 0.f ? v3 : (expf(v3) - 1.f);
            } else if (act == 2) {
                v0 = v0 / (1.f + expf(-v0));
                v1 = v1 / (1.f + expf(-v1));
                v2 = v2 / (1.f + expf(-v2));
                v3 = v3 / (1.f + expf(-v3));
            }
            *(float2*)(C + (size_t)rm * 2048 + cn) = make_float2(v0, v1);
            *(float2*)(C + (size_t)(rm + 8) * 2048 + cn) = make_float2(v2, v3);
        }
    }
}

// ---------------------------------------------------------------------------
// prep kernels
// ---------------------------------------------------------------------------
__global__ void split_kernel(const float* __restrict__ x,
                             __half* __restrict__ h, __half* __restrict__ l, int n4) {
    int i = blockIdx.x * blockDim.x + threadIdx.x;
    if (i >= n4) return;
    float4 v = ((const float4*)x)[i];
    __half h0 = __float2half(v.x), h1 = __float2half(v.y);
    __half h2 = __float2half(v.z), h3 = __float2half(v.w);
    __half2* hp = (__half2*)h;
    __half2* lp = (__half2*)l;
    hp[i * 2 + 0] = __halves2half2(h0, h1);
    hp[i * 2 + 1] = __halves2half2(h2, h3);
    lp[i * 2 + 0] = __halves2half2(__float2half(v.x - __half2float(h0)),
                                   __float2half(v.y - __half2float(h1)));
    lp[i * 2 + 1] = __halves2half2(__float2half(v.z - __half2float(h2)),
                                   __float2half(v.w - __half2float(h3)));
}

// 4 weight matrices W[K,N] fp32 -> T[N,K] single fp16, one launch (grid.z selects W)
struct TsplitBatch {
    const float* W[4];
    __half* T[4];
};
__global__ void tsplit_kernel(TsplitBatch P) {
    __shared__ float tile[32][33];
    const float* __restrict__ W = P.W[blockIdx.z];
    __half* __restrict__ T = P.T[blockIdx.z];
    const int k0 = blockIdx.y * 32, n0 = blockIdx.x * 32;
    const int tx = threadIdx.x, ty = threadIdx.y;
#pragma unroll
    for (int i = 0; i < 32; i += 8)
        tile[ty + i][tx] = W[(size_t)(k0 + ty + i) * 2048 + n0 + tx];
    __syncthreads();
#pragma unroll
    for (int i = 0; i < 32; i += 8)
        T[(size_t)(n0 + ty + i) * 2048 + k0 + tx] = __float2half(tile[tx][ty + i]);
}

// ---------------------------------------------------------------------------
// kv = q^T v per (b,h), split over sequence (fp32 SIMT)
// ---------------------------------------------------------------------------
__global__ void kv_kernel() {
    __shared__ float qs[16][128];
    __shared__ float vs[16][128];
    const int bh = blockIdx.x;
    const int b = bh / HEADS, h = bh % HEADS;
    const int split = blockIdx.y;
    const int chunk = SEQ / SPLITS;          // 1024
    const int n0 = split * chunk;
    const int tid = threadIdx.x;
    const int tx = tid & 15, ty = tid >> 4;
    const size_t base = (size_t)(b * SEQ) * HD + h * DHd;

    float acc[8][8] = {};
    for (int nt = 0; nt < chunk; nt += 16) {
#pragma unroll
        for (int l = 0; l < 2; l++) {
            const int idx = tid + l * 256;
            const int r = idx >> 5;
            const int c = (idx & 31) * 4;
            const size_t off = base + (size_t)(n0 + nt + r) * HD + c;
            *(float4*)&qs[r][c] = *(const float4*)(g_q + off);
            *(float4*)&vs[r][c] = *(const float4*)(g_v + off);
        }
        __syncthreads();
#pragma unroll
        for (int kk = 0; kk < 16; kk++) {
            float rq[8], rv[8];
#pragma unroll
            for (int i = 0; i < 8; i++) rq[i] = qs[kk][ty * 8 + i];
#pragma unroll
            for (int j = 0; j < 8; j++) rv[j] = vs[kk][tx * 8 + j];
#pragma unroll
            for (int i = 0; i < 8; i++)
#pragma unroll
                for (int j = 0; j < 8; j++)
                    acc[i][j] += rq[i] * rv[j];
        }
        __syncthreads();
    }
    float* kvp = g_kv + ((size_t)split * Bn * HEADS + bh) * DHd * DHd;
#pragma unroll
    for (int i = 0; i < 8; i++)
#pragma unroll
        for (int j = 0; j < 8; j++)
            kvp[(ty * 8 + i) * DHd + tx * 8 + j] = acc[i][j];
}

// ---------------------------------------------------------------------------
// reduce SPLITS kv slices -> g_kvsum
// ---------------------------------------------------------------------------
__global__ void kvsum_kernel() {
    const int n4 = Bn * HEADS * DHd * DHd / 4;
    const size_t stride4 = (size_t)Bn * HEADS * DHd * DHd / 4;
    int i = blockIdx.x * blockDim.x + threadIdx.x;
    if (i >= n4) return;
    const float4* src = (const float4*)g_kv;
    float4 s = src[i];
#pragma unroll
    for (int sp = 1; sp < SPLITS; sp++) {
        float4 t = src[i + sp * stride4];
        s.x += t.x; s.y += t.y; s.z += t.z; s.w += t.w;
    }
    ((float4*)g_kvsum)[i] = s;
}

// ---------------------------------------------------------------------------
// out = q @ kvsum per (b,h) (fp32 SIMT)
// ---------------------------------------------------------------------------
__global__ void out_kernel() {
    __shared__ float As[16][64];
    __shared__ float Bs[16][128];
    const int m0 = blockIdx.x * 64;
    const int h = blockIdx.y;
    const int b = m0 / SEQ;
    const int tid = threadIdx.x;
    const int tx = tid & 15, ty = tid >> 4;
    const size_t kvoff = (size_t)(b * HEADS + h) * DHd * DHd;

    float acc[4][8] = {};
    const int a_r = tid >> 2;
    const int a_s = (tid & 3) * 4;

    for (int k0 = 0; k0 < DHd; k0 += 16) {
        float4 av = *(const float4*)(g_q + (size_t)(m0 + a_r) * HD + h * DHd + k0 + a_s);
        As[a_s + 0][a_r] = av.x;
        As[a_s + 1][a_r] = av.y;
        As[a_s + 2][a_r] = av.z;
        As[a_s + 3][a_r] = av.w;
#pragma unroll
        for (int l = 0; l < 2; l++) {
            const int idx = tid + l * 256;
            const int r = idx >> 5;
            const int c = (idx & 31) * 4;
            *(float4*)&Bs[r][c] = *(const float4*)(g_kvsum + kvoff + (size_t)(k0 + r) * DHd + c);
        }
        __syncthreads();
#pragma unroll
        for (int kk = 0; kk < 16; kk++) {
            float ra[4], rb[8];
#pragma unroll
            for (int i = 0; i < 4; i++) ra[i] = As[kk][ty * 4 + i];
#pragma unroll
            for (int j = 0; j < 8; j++) rb[j] = Bs[kk][tx * 8 + j];
#pragma unroll
            for (int i = 0; i < 4; i++)
#pragma unroll
                for (int j = 0; j < 8; j++)
                    acc[i][j] += ra[i] * rb[j];
        }
        __syncthreads();
    }
#pragma unroll
    for (int i = 0; i < 4; i++)
#pragma unroll
        for (int j = 0; j < 8; j++)
            g_o[(size_t)(m0 + ty * 4 + i) * HD + h * DHd + tx * 8 + j] = acc[i][j];
}

// ---------------------------------------------------------------------------
// LayerNorm over HD, * gate u, emit fp16 hi/lo for final GEMM
// ---------------------------------------------------------------------------
__global__ void ln_mul_kernel(const float* __restrict__ lng, const float* __restrict__ lnb) {
    __shared__ float buf[HD];
    __shared__ float red[256];
    const int row = blockIdx.x;
    const int tid = threadIdx.x;
    const float* orow = g_o + (size_t)row * HD;
    const float* urow = g_u + (size_t)row * HD;

    float s = 0.f;
    for (int c = tid; c < HD; c += 256) { float v = orow[c]; buf[c] = v; s += v; }
    red[tid] = s; __syncthreads();
    for (int off = 128; off; off >>= 1) { if (tid < off) red[tid] += red[tid + off]; __syncthreads(); }
    const float mean = red[0] * (1.f / HD);
    __syncthreads();

    float s2 = 0.f;
    for (int c = tid; c < HD; c += 256) { float d = buf[c] - mean; s2 += d * d; }
    red[tid] = s2; __syncthreads();
    for (int off = 128; off; off >>= 1) { if (tid < off) red[tid] += red[tid + off]; __syncthreads(); }
    const float rstd = rsqrtf(red[0] * (1.f / HD) + 1e-5f);

    for (int c = tid; c < HD; c += 256) {
        float v = ((buf[c] - mean) * rstd * lng[c] + lnb[c]) * urow[c];
        __half hv = __float2half(v);
        g_lnh[(size_t)row * HD + c] = hv;
        g_lnl[(size_t)row * HD + c] = __float2half(v - __half2float(hv));
    }
}

// ---------------------------------------------------------------------------
// launch
// ---------------------------------------------------------------------------
extern "C" void kernel_launch(void* const* d_in, const int* in_sizes, int n_in,
                              void* d_out, int out_size) {
    const float* x   = (const float*)d_in[0];
    const float* Wqk = (const float*)d_in[1];
    const float* bqk = (const float*)d_in[2];
    const float* Wv  = (const float*)d_in[3];
    const float* bv  = (const float*)d_in[4];
    const float* Wu  = (const float*)d_in[5];
    const float* bu  = (const float*)d_in[6];
    const float* Wo  = (const float*)d_in[7];
    const float* bo  = (const float*)d_in[8];
    const float* lng = (const float*)d_in[9];
    const float* lnb = (const float*)d_in[10];
    float* out = (float*)d_out;

    float *pq, *pv, *pu;
    __half *pxh, *pxl, *plnh, *plnl, *pwqk, *pwv, *pwu, *pwo;
    cudaGetSymbolAddress((void**)&pq, g_q);
    cudaGetSymbolAddress((void**)&pv, g_v);
    cudaGetSymbolAddress((void**)&pu, g_u);
    cudaGetSymbolAddress((void**)&pxh, g_xh);
    cudaGetSymbolAddress((void**)&pxl, g_xl);
    cudaGetSymbolAddress((void**)&plnh, g_lnh);
    cudaGetSymbolAddress((void**)&plnl, g_lnl);
    cudaGetSymbolAddress((void**)&pwqk, g_wqk);
    cudaGetSymbolAddress((void**)&pwv, g_wv);
    cudaGetSymbolAddress((void**)&pwu, g_wu);
    cudaGetSymbolAddress((void**)&pwo, g_wo);

    cudaFuncSetAttribute(gemm_f16_2p, cudaFuncAttributeMaxDynamicSharedMemorySize, GEMM_SMEM);

    // prep: split x; transpose 4 weights to fp16 in one launch
    {
        int n4 = MR * Ein / 4;
        split_kernel<<<(n4 + 255) / 256, 256>>>(x, pxh, pxl, n4);
        TsplitBatch T;
        T.W[0] = Wqk; T.T[0] = pwqk;
        T.W[1] = Wv;  T.T[1] = pwv;
        T.W[2] = Wu;  T.T[2] = pwu;
        T.W[3] = Wo;  T.T[3] = pwo;
        tsplit_kernel<<<dim3(64, 64, 4), dim3(32, 8)>>>(T);
    }

    // merged q/v/u GEMM: z=0 q(elu), z=1 v(silu), z=2 u(silu)
    {
        GemmBatch P;
        P.B[0] = pwqk; P.bias[0] = bqk; P.C[0] = pq; P.act[0] = 1;
        P.B[1] = pwv;  P.bias[1] = bv;  P.C[1] = pv; P.act[1] = 2;
        P.B[2] = pwu;  P.bias[2] = bu;  P.C[2] = pu; P.act[2] = 2;
        dim3 g3(HD / BN, MR / BM, 3);     // (16, 128, 3)
        gemm_f16_2p<<<g3, 256, GEMM_SMEM>>>(pxh, pxl, P);
    }

    // linear attention
    kv_kernel<<<dim3(Bn * HEADS, SPLITS), 256>>>();
    kvsum_kernel<<<(Bn * HEADS * DHd * DHd / 4 + 255) / 256, 256>>>();
    out_kernel<<<dim3(MR / 64, HEADS), 256>>>();

    // LN * gate -> fp16 hi/lo
    ln_mul_kernel<<<MR, 256>>>(lng, lnb);

    // y = ln_out @ Wo + bo
    {
        GemmBatch P;
        P.B[0] = pwo; P.bias[0] = bo; P.C[0] = out; P.act[0] = 0;
        dim3 g1(HD / BN, MR / BM, 1);
        gemm_f16_2p<<<g1, 256, GEMM_SMEM>>>(plnh, plnl, P);
    }
}

// round 15
// speedup vs baseline: 2.5657x; 1.1545x over previous
#include <cuda_runtime.h>
#include <cuda_fp16.h>
#include <cstdint>
#include <math.h>

#define Bn    4
#define SEQ   4096
#define Ein   2048
#define HD    2048
#define HEADS 16
#define DHd   128
#define MR    (Bn * SEQ)      // 16384
#define SPLITS 4

// ---------------------------------------------------------------------------
// PTX helpers (base-target safe: sm_80+ instructions only)
// ---------------------------------------------------------------------------
__device__ __forceinline__ uint32_t smem_u32(const void* p) {
    uint32_t a;
    asm("{ .reg .u64 t; cvta.to.shared.u64 t, %1; cvt.u32.u64 %0, t; }" : "=r"(a) : "l"(p));
    return a;
}

#define CP16(dst, src) \
    asm volatile("cp.async.cg.shared.global [%0], [%1], 16;" :: "r"(dst), "l"(src) : "memory")
#define CP_COMMIT() asm volatile("cp.async.commit_group;" ::: "memory")
#define CP_WAIT(n)  asm volatile("cp.async.wait_group %0;" :: "n"(n) : "memory")

#define LDMX4(r, addr) \
    asm volatile("ldmatrix.sync.aligned.m8n8.x4.shared.b16 {%0,%1,%2,%3}, [%4];" \
        : "=r"((r)[0]), "=r"((r)[1]), "=r"((r)[2]), "=r"((r)[3]) : "r"(addr))

#define LDMX4T(r, addr) \
    asm volatile("ldmatrix.sync.aligned.m8n8.x4.trans.shared.b16 {%0,%1,%2,%3}, [%4];" \
        : "=r"((r)[0]), "=r"((r)[1]), "=r"((r)[2]), "=r"((r)[3]) : "r"(addr))

#define MMA_F16(d, a, b0v, b1v) \
    asm volatile("mma.sync.aligned.m16n8k16.row.col.f32.f16.f16.f32 " \
        "{%0,%1,%2,%3}, {%4,%5,%6,%7}, {%8,%9}, {%0,%1,%2,%3};" \
        : "+f"((d)[0]), "+f"((d)[1]), "+f"((d)[2]), "+f"((d)[3]) \
        : "r"((a)[0]), "r"((a)[1]), "r"((a)[2]), "r"((a)[3]), "r"(b0v), "r"(b1v))

// ---------------------------------------------------------------------------
// scratch (device globals; no allocation allowed)
// ---------------------------------------------------------------------------
__device__ float g_u [MR * HD];
__device__ float g_o [MR * HD];
__device__ float g_kv[SPLITS * Bn * HEADS * DHd * DHd];
__device__ __half g_kvh[Bn * HEADS * DHd * DHd];          // kv^T hi [bh][e][d]
__device__ __half g_kvl[Bn * HEADS * DHd * DHd];          // kv^T lo
__device__ __half g_qh [MR * HD], g_ql[MR * HD];          // elu(q) hi/lo
__device__ __half g_vh [MR * HD];                         // silu(v) fp16
__device__ __half g_xh [MR * Ein], g_xl[MR * Ein];
__device__ __half g_lnh[MR * HD], g_lnl[MR * HD];
__device__ __half g_wqk[HD * Ein];                        // [N][K] transposed fp16
__device__ __half g_wv [HD * Ein];
__device__ __half g_wu [HD * Ein];
__device__ __half g_wo [Ein * HD];

// ---------------------------------------------------------------------------
// batched fp16 2-product GEMM: C[z] = act[z]( (Ah+Al) @ B[z]^T + bias[z] )
// BM=128 BN=128 BK=32, 3-stage cp.async ring, 8 warps (2m x 4n), warp 64x32.
// Output modes: 0 = fp32, 1 = fp16 hi/lo pair, 2 = fp16 single.
// NOTE: CP_COMMIT issued EVERY iteration (empty in tail) so wait_group(1)
// always proves the compute stage is resident — tail race fix.
// ---------------------------------------------------------------------------
#define BM 128
#define BN 128
#define BK 32
#define STAGES 3
#define OFF_AH 0
#define OFF_AL 8192
#define OFF_B  16384
#define STG_BYTES 24576
#define GEMM_SMEM (STAGES * STG_BYTES)           // 73728
#define NIT (2048 / BK)                          // 64

struct GemmBatch {
    const __half* B[3];
    const float* bias[3];
    float* C[3];
    __half* Ch[3];
    __half* Cl[3];
    int mode[3];
    int act[3];      // 0 none, 1 elu, 2 silu
};

__global__ void __launch_bounds__(256, 2) gemm_f16_2p(
    const __half* __restrict__ Ah, const __half* __restrict__ Al,
    GemmBatch P)
{
    extern __shared__ char smem[];
    const uint32_t sb = smem_u32(smem);
    const int tid = threadIdx.x;
    const int m0 = blockIdx.y * BM;
    const int n0 = blockIdx.x * BN;
    const int z  = blockIdx.z;
    const __half* __restrict__ Bp0 = P.B[z];

    const int lane = tid & 31, w = tid >> 5;
    const int wm = (w >> 2) * 64;
    const int wn = (w & 3) * 32;
    const int mi = lane >> 3, rowin = lane & 7;

    const int au = mi >> 1, aro = (mi & 1) << 3;
    uint32_t aoff[4]; int arx[4];
#pragma unroll
    for (int mt = 0; mt < 4; mt++) {
        int r = wm + mt * 16 + aro + rowin;
        aoff[mt] = r * 64;
        arx[mt] = (r >> 1) & 3;
    }
    const int bu = mi & 1, bro = (mi >> 1) << 3;
    uint32_t boff[2]; int brx[2];
#pragma unroll
    for (int p = 0; p < 2; p++) {
        int r = wn + p * 16 + bro + rowin;
        boff[p] = OFF_B + r * 64;
        brx[p] = (r >> 1) & 3;
    }

    const int lr = tid >> 2, lu = tid & 3;
    const uint32_t sw0 = (uint32_t)(lr * 64 + ((lu ^ ((lr >> 1) & 3)) << 4));
    const __half* Ahp = Ah + (size_t)(m0 + lr) * 2048 + lu * 8;
    const __half* Alp = Al + (size_t)(m0 + lr) * 2048 + lu * 8;
    const __half* Bpp = Bp0 + (size_t)(n0 + lr) * 2048 + lu * 8;

    float acc[4][4][4] = {};

#pragma unroll
    for (int s = 0; s < STAGES - 1; s++) {
        const uint32_t st = sb + s * STG_BYTES;
        const int k0 = s * BK;
        CP16(st + OFF_AH + sw0,        Ahp + k0);
        CP16(st + OFF_AH + sw0 + 4096, Ahp + k0 + (size_t)64 * 2048);
        CP16(st + OFF_AL + sw0,        Alp + k0);
        CP16(st + OFF_AL + sw0 + 4096, Alp + k0 + (size_t)64 * 2048);
        CP16(st + OFF_B  + sw0,        Bpp + k0);
        CP16(st + OFF_B  + sw0 + 4096, Bpp + k0 + (size_t)64 * 2048);
        CP_COMMIT();
    }

    int cs = 0, ls = STAGES - 1;
    for (int it = 0; it < NIT; it++) {
        CP_WAIT(STAGES - 2);
        __syncthreads();

        const int nx = it + STAGES - 1;
        if (nx < NIT) {
            const uint32_t st2 = sb + ls * STG_BYTES;
            const int k0 = nx * BK;
            CP16(st2 + OFF_AH + sw0,        Ahp + k0);
            CP16(st2 + OFF_AH + sw0 + 4096, Ahp + k0 + (size_t)64 * 2048);
            CP16(st2 + OFF_AL + sw0,        Alp + k0);
            CP16(st2 + OFF_AL + sw0 + 4096, Alp + k0 + (size_t)64 * 2048);
            CP16(st2 + OFF_B  + sw0,        Bpp + k0);
            CP16(st2 + OFF_B  + sw0 + 4096, Bpp + k0 + (size_t)64 * 2048);
        }
        CP_COMMIT();   // unconditional: keeps group-count arithmetic valid in tail

        const uint32_t st = sb + cs * STG_BYTES;
#pragma unroll
        for (int ks = 0; ks < 2; ks++) {
            uint32_t bb[2][4];
#pragma unroll
            for (int p = 0; p < 2; p++)
                LDMX4(bb[p], st + boff[p] + (uint32_t)(((2 * ks + bu) ^ brx[p]) << 4));
            uint32_t ah[4][4];
#pragma unroll
            for (int mt = 0; mt < 4; mt++)
                LDMX4(ah[mt], st + OFF_AH + aoff[mt] + (uint32_t)(((2 * ks + au) ^ arx[mt]) << 4));
#pragma unroll
            for (int mt = 0; mt < 4; mt++)
#pragma unroll
                for (int nt = 0; nt < 4; nt++)
                    MMA_F16(acc[mt][nt], ah[mt], bb[nt >> 1][(nt & 1) * 2], bb[nt >> 1][(nt & 1) * 2 + 1]);
#pragma unroll
            for (int mt = 0; mt < 4; mt++)
                LDMX4(ah[mt], st + OFF_AL + aoff[mt] + (uint32_t)(((2 * ks + au) ^ arx[mt]) << 4));
#pragma unroll
            for (int mt = 0; mt < 4; mt++)
#pragma unroll
                for (int nt = 0; nt < 4; nt++)
                    MMA_F16(acc[mt][nt], ah[mt], bb[nt >> 1][(nt & 1) * 2], bb[nt >> 1][(nt & 1) * 2 + 1]);
        }
        if (++cs == STAGES) cs = 0;
        if (++ls == STAGES) ls = 0;
    }

    // -------- epilogue --------
    const float* __restrict__ bias = P.bias[z];
    const int act = P.act[z];
    const int mode = P.mode[z];
    const int g = lane >> 2, t = lane & 3;
#pragma unroll
    for (int mt = 0; mt < 4; mt++) {
#pragma unroll
        for (int nt = 0; nt < 4; nt++) {
            const int rm = m0 + wm + mt * 16 + g;
            const int cn = n0 + wn + nt * 8 + 2 * t;
            const float b0 = bias[cn], b1 = bias[cn + 1];
            float v0 = acc[mt][nt][0] + b0;
            float v1 = acc[mt][nt][1] + b1;
            float v2 = acc[mt][nt][2] + b0;
            float v3 = acc[mt][nt][3] + b1;
            if (act == 1) {
                v0 = v0 > 0.f ? v0 : (expf(v0) - 1.f);
                v1 = v1 > 0.f ? v1 : (expf(v1) - 1.f);
                v2 = v2 > 0.f ? v2 : (expf(v2) - 1.f);
                v3 = v3 > 0.f ? v3 : (expf(v3) - 1.f);
            } else if (act == 2) {
                v0 = v0 / (1.f + expf(-v0));
                v1 = v1 / (1.f + expf(-v1));
                v2 = v2 / (1.f + expf(-v2));
                v3 = v3 / (1.f + expf(-v3));
            }
            if (mode == 0) {
                float* C = P.C[z];
                *(float2*)(C + (size_t)rm * 2048 + cn) = make_float2(v0, v1);
                *(float2*)(C + (size_t)(rm + 8) * 2048 + cn) = make_float2(v2, v3);
            } else {
                __half* Ch = P.Ch[z];
                __half h0 = __float2half(v0), h1 = __float2half(v1);
                __half h2 = __float2half(v2), h3 = __float2half(v3);
                *(__half2*)(Ch + (size_t)rm * 2048 + cn) = __halves2half2(h0, h1);
                *(__half2*)(Ch + (size_t)(rm + 8) * 2048 + cn) = __halves2half2(h2, h3);
                if (mode == 1) {
                    __half* Cl = P.Cl[z];
                    *(__half2*)(Cl + (size_t)rm * 2048 + cn) =
                        __halves2half2(__float2half(v0 - __half2float(h0)),
                                       __float2half(v1 - __half2float(h1)));
                    *(__half2*)(Cl + (size_t)(rm + 8) * 2048 + cn) =
                        __halves2half2(__float2half(v2 - __half2float(h2)),
                                       __float2half(v3 - __half2float(h3)));
                }
            }
        }
    }
}

// ---------------------------------------------------------------------------
// kv_tc: kvT[bh][e][d] slice = V^T (Qh+Ql) over one seq split, tensor cores.
// A = vh (m=e, trans-ldmatrix), B = qh/ql (n=d, trans-ldmatrix), K = seq.
// Same unconditional-commit tail fix.
// ---------------------------------------------------------------------------
#define KV_OQH 0
#define KV_OQL 8192
#define KV_OVH 16384
#define KV_STGB 24576
#define KV_SMEM (3 * KV_STGB)     // 73728

__global__ void __launch_bounds__(256, 2) kv_tc() {
    extern __shared__ char smem[];
    const uint32_t sb = smem_u32(smem);
    const int tid = threadIdx.x;
    const int bh = blockIdx.x;
    const int b = bh >> 4, h = bh & 15;
    const int seq0 = blockIdx.y * (SEQ / SPLITS);   // 1024-chunk
    const int lane = tid & 31, w = tid >> 5;
    const int wm = (w >> 2) * 64;      // e
    const int wn = (w & 3) * 32;       // d
    const int mi = lane >> 3, rowin = lane & 7;

    const int rowA = ((mi >> 1) << 3) + rowin;
    const int rowB = ((mi & 1) << 3) + rowin;
    uint32_t cA[4], cB[2];
#pragma unroll
    for (int mt = 0; mt < 4; mt++)
        cA[mt] = (uint32_t)((((wm + mt * 16 + ((mi & 1) << 3)) >> 3) ^ rowin) << 4);
#pragma unroll
    for (int p = 0; p < 2; p++)
        cB[p] = (uint32_t)((((wn + p * 16 + ((mi >> 1) << 3)) >> 3) ^ rowin) << 4);

    const int lr = tid >> 3, lc = tid & 7;
    const uint32_t dA = (uint32_t)(lr * 256 + ((lc ^ (lr & 7)) << 4));
    const uint32_t dB = (uint32_t)(lr * 256 + (((lc + 8) ^ (lr & 7)) << 4));
    const size_t g0 = (size_t)(b * SEQ + seq0 + lr) * 2048 + h * 128;

    float acc[4][4][4] = {};

#pragma unroll
    for (int s = 0; s < 2; s++) {
        const uint32_t st = sb + s * KV_STGB;
        const size_t go = g0 + (size_t)(s * 32) * 2048;
        CP16(st + KV_OQH + dA, g_qh + go + lc * 8);
        CP16(st + KV_OQH + dB, g_qh + go + (lc + 8) * 8);
        CP16(st + KV_OQL + dA, g_ql + go + lc * 8);
        CP16(st + KV_OQL + dB, g_ql + go + (lc + 8) * 8);
        CP16(st + KV_OVH + dA, g_vh + go + lc * 8);
        CP16(st + KV_OVH + dB, g_vh + go + (lc + 8) * 8);
        CP_COMMIT();
    }

    int cs = 0, ls = 2;
    for (int it = 0; it < 32; it++) {
        CP_WAIT(1);
        __syncthreads();
        const int nx = it + 2;
        if (nx < 32) {
            const uint32_t st2 = sb + ls * KV_STGB;
            const size_t go = g0 + (size_t)(nx * 32) * 2048;
            CP16(st2 + KV_OQH + dA, g_qh + go + lc * 8);
            CP16(st2 + KV_OQH + dB, g_qh + go + (lc + 8) * 8);
            CP16(st2 + KV_OQL + dA, g_ql + go + lc * 8);
            CP16(st2 + KV_OQL + dB, g_ql + go + (lc + 8) * 8);
            CP16(st2 + KV_OVH + dA, g_vh + go + lc * 8);
            CP16(st2 + KV_OVH + dB, g_vh + go + (lc + 8) * 8);
        }
        CP_COMMIT();   // unconditional (tail race fix)
        const uint32_t st = sb + cs * KV_STGB;
#pragma unroll
        for (int ks = 0; ks < 2; ks++) {
            uint32_t av[4][4];
#pragma unroll
            for (int mt = 0; mt < 4; mt++)
                LDMX4T(av[mt], st + KV_OVH + (uint32_t)((ks * 16 + rowA) * 256) + cA[mt]);
            uint32_t bq[2][4];
#pragma unroll
            for (int p = 0; p < 2; p++)
                LDMX4T(bq[p], st + KV_OQH + (uint32_t)((ks * 16 + rowB) * 256) + cB[p]);
#pragma unroll
            for (int mt = 0; mt < 4; mt++)
#pragma unroll
                for (int nt = 0; nt < 4; nt++)
                    MMA_F16(acc[mt][nt], av[mt], bq[nt >> 1][(nt & 1) * 2], bq[nt >> 1][(nt & 1) * 2 + 1]);
#pragma unroll
            for (int p = 0; p < 2; p++)
                LDMX4T(bq[p], st + KV_OQL + (uint32_t)((ks * 16 + rowB) * 256) + cB[p]);
#pragma unroll
            for (int mt = 0; mt < 4; mt++)
#pragma unroll
                for (int nt = 0; nt < 4; nt++)
                    MMA_F16(acc[mt][nt], av[mt], bq[nt >> 1][(nt & 1) * 2], bq[nt >> 1][(nt & 1) * 2 + 1]);
        }
        if (++cs == 3) cs = 0;
        if (++ls == 3) ls = 0;
    }

    float* kvp = g_kv + ((size_t)blockIdx.y * Bn * HEADS + bh) * DHd * DHd;
    const int g = lane >> 2, t = lane & 3;
#pragma unroll
    for (int mt = 0; mt < 4; mt++)
#pragma unroll
        for (int nt = 0; nt < 4; nt++) {
            const int rm = wm + mt * 16 + g;
            const int cn = wn + nt * 8 + 2 * t;
            *(float2*)(kvp + rm * 128 + cn) = make_float2(acc[mt][nt][0], acc[mt][nt][1]);
            *(float2*)(kvp + (rm + 8) * 128 + cn) = make_float2(acc[mt][nt][2], acc[mt][nt][3]);
        }
}

// ---------------------------------------------------------------------------
// kvsum: sum SPLITS fp32 slices -> fp16 hi/lo pair
// ---------------------------------------------------------------------------
__global__ void kvsum_kernel() {
    const int n4 = Bn * HEADS * DHd * DHd / 4;      // 262144
    int i = blockIdx.x * blockDim.x + threadIdx.x;
    if (i >= n4) return;
    const float4* src = (const float4*)g_kv;
    float4 s = src[i];
#pragma unroll
    for (int sp = 1; sp < SPLITS; sp++) {
        float4 t = src[i + (size_t)sp * n4];
        s.x += t.x; s.y += t.y; s.z += t.z; s.w += t.w;
    }
    __half h0 = __float2half(s.x), h1 = __float2half(s.y);
    __half h2 = __float2half(s.z), h3 = __float2half(s.w);
    __half2* dh = (__half2*)g_kvh;
    __half2* dl = (__half2*)g_kvl;
    dh[i * 2 + 0] = __halves2half2(h0, h1);
    dh[i * 2 + 1] = __halves2half2(h2, h3);
    dl[i * 2 + 0] = __halves2half2(__float2half(s.x - __half2float(h0)),
                                   __float2half(s.y - __half2float(h1)));
    dl[i * 2 + 1] = __halves2half2(__float2half(s.z - __half2float(h2)),
                                   __float2half(s.w - __half2float(h3)));
}

// ---------------------------------------------------------------------------
// out_tc: o[m][e] = (Qh+Ql)[m][d] @ (Kh+Kl)T[e][d]  (3-product, drop QlKl).
// Monolithic 128KB smem (qh|ql|kvh|kvl of 32KB), K=128, 8 k-iters. 1 CTA/SM.
// ---------------------------------------------------------------------------
#define OT_OQH 0
#define OT_OQL 32768
#define OT_OKH 65536
#define OT_OKL 98304
#define OT_SMEM 131072

__global__ void __launch_bounds__(256) out_tc() {
    extern __shared__ char smem[];
    const uint32_t sb = smem_u32(smem);
    const int tid = threadIdx.x;
    const int m0 = blockIdx.x * 128;
    const int h = blockIdx.y;
    const int b = m0 >> 12;
    const int lane = tid & 31, w = tid >> 5;
    const int wm = (w >> 2) * 64;
    const int wn = (w & 3) * 32;
    const int mi = lane >> 3, rowin = lane & 7;

#pragma unroll
    for (int i = 0; i < 8; i++) {
        const int widx = tid + i * 256;
        const int row = widx >> 4, c = widx & 15;
        const uint32_t dst = (uint32_t)(row * 256 + ((c ^ (row & 7)) << 4));
        CP16(sb + OT_OQH + dst, g_qh + (size_t)(m0 + row) * 2048 + h * 128 + c * 8);
        CP16(sb + OT_OQL + dst, g_ql + (size_t)(m0 + row) * 2048 + h * 128 + c * 8);
        CP16(sb + OT_OKH + dst, g_kvh + (size_t)(b * HEADS + h) * 16384 + row * 128 + c * 8);
        CP16(sb + OT_OKL + dst, g_kvl + (size_t)(b * HEADS + h) * 16384 + row * 128 + c * 8);
    }
    CP_COMMIT();
    CP_WAIT(0);
    __syncthreads();

    const int arow_ = ((mi & 1) << 3) + rowin;
    const int akc = mi >> 1;
    const int brow_ = ((mi >> 1) << 3) + rowin;
    const int bkc = mi & 1;

    float acc[4][4][4] = {};
#pragma unroll
    for (int kt = 0; kt < 8; kt++) {
        uint32_t bb[2][4];
#pragma unroll
        for (int p = 0; p < 2; p++) {
            const int row = wn + p * 16 + brow_;
            LDMX4(bb[p], sb + OT_OKH + (uint32_t)(row * 256) + (uint32_t)(((kt * 2 + bkc) ^ rowin) << 4));
        }
        uint32_t ahh[4][4];
#pragma unroll
        for (int mt = 0; mt < 4; mt++) {
            const int row = wm + mt * 16 + arow_;
            LDMX4(ahh[mt], sb + OT_OQH + (uint32_t)(row * 256) + (uint32_t)(((kt * 2 + akc) ^ rowin) << 4));
        }
        // Qh * Kh
#pragma unroll
        for (int mt = 0; mt < 4; mt++)
#pragma unroll
            for (int nt = 0; nt < 4; nt++)
                MMA_F16(acc[mt][nt], ahh[mt], bb[nt >> 1][(nt & 1) * 2], bb[nt >> 1][(nt & 1) * 2 + 1]);
        // Ql * Kh
        {
            uint32_t ahl[4][4];
#pragma unroll
            for (int mt = 0; mt < 4; mt++) {
                const int row = wm + mt * 16 + arow_;
                LDMX4(ahl[mt], sb + OT_OQL + (uint32_t)(row * 256) + (uint32_t)(((kt * 2 + akc) ^ rowin) << 4));
            }
#pragma unroll
            for (int mt = 0; mt < 4; mt++)
#pragma unroll
                for (int nt = 0; nt < 4; nt++)
                    MMA_F16(acc[mt][nt], ahl[mt], bb[nt >> 1][(nt & 1) * 2], bb[nt >> 1][(nt & 1) * 2 + 1]);
        }
        // Qh * Kl (reuse bb)
#pragma unroll
        for (int p = 0; p < 2; p++) {
            const int row = wn + p * 16 + brow_;
            LDMX4(bb[p], sb + OT_OKL + (uint32_t)(row * 256) + (uint32_t)(((kt * 2 + bkc) ^ rowin) << 4));
        }
#pragma unroll
        for (int mt = 0; mt < 4; mt++)
#pragma unroll
            for (int nt = 0; nt < 4; nt++)
                MMA_F16(acc[mt][nt], ahh[mt], bb[nt >> 1][(nt & 1) * 2], bb[nt >> 1][(nt & 1) * 2 + 1]);
    }

    const int g = lane >> 2, t = lane & 3;
#pragma unroll
    for (int mt = 0; mt < 4; mt++)
#pragma unroll
        for (int nt = 0; nt < 4; nt++) {
            const int rm = m0 + wm + mt * 16 + g;
            const int cn = h * 128 + wn + nt * 8 + 2 * t;
            *(float2*)(g_o + (size_t)rm * 2048 + cn) = make_float2(acc[mt][nt][0], acc[mt][nt][1]);
            *(float2*)(g_o + (size_t)(rm + 8) * 2048 + cn) = make_float2(acc[mt][nt][2], acc[mt][nt][3]);
        }
}

// ---------------------------------------------------------------------------
// prep kernels
// ---------------------------------------------------------------------------
__global__ void split_kernel(const float* __restrict__ x,
                             __half* __restrict__ h, __half* __restrict__ l, int n4) {
    int i = blockIdx.x * blockDim.x + threadIdx.x;
    if (i >= n4) return;
    float4 v = ((const float4*)x)[i];
    __half h0 = __float2half(v.x), h1 = __float2half(v.y);
    __half h2 = __float2half(v.z), h3 = __float2half(v.w);
    __half2* hp = (__half2*)h;
    __half2* lp = (__half2*)l;
    hp[i * 2 + 0] = __halves2half2(h0, h1);
    hp[i * 2 + 1] = __halves2half2(h2, h3);
    lp[i * 2 + 0] = __halves2half2(__float2half(v.x - __half2float(h0)),
                                   __float2half(v.y - __half2float(h1)));
    lp[i * 2 + 1] = __halves2half2(__float2half(v.z - __half2float(h2)),
                                   __float2half(v.w - __half2float(h3)));
}

struct TsplitBatch {
    const float* W[4];
    __half* T[4];
};
__global__ void tsplit_kernel(TsplitBatch P) {
    __shared__ float tile[32][33];
    const float* __restrict__ W = P.W[blockIdx.z];
    __half* __restrict__ T = P.T[blockIdx.z];
    const int k0 = blockIdx.y * 32, n0 = blockIdx.x * 32;
    const int tx = threadIdx.x, ty = threadIdx.y;
#pragma unroll
    for (int i = 0; i < 32; i += 8)
        tile[ty + i][tx] = W[(size_t)(k0 + ty + i) * 2048 + n0 + tx];
    __syncthreads();
#pragma unroll
    for (int i = 0; i < 32; i += 8)
        T[(size_t)(n0 + ty + i) * 2048 + k0 + tx] = __float2half(tile[tx][ty + i]);
}

// ---------------------------------------------------------------------------
// LayerNorm over HD, * gate u, emit fp16 hi/lo for final GEMM
// ---------------------------------------------------------------------------
__global__ void ln_mul_kernel(const float* __restrict__ lng, const float* __restrict__ lnb) {
    __shared__ float buf[HD];
    __shared__ float red[256];
    const int row = blockIdx.x;
    const int tid = threadIdx.x;
    const float* orow = g_o + (size_t)row * HD;
    const float* urow = g_u + (size_t)row * HD;

    float s = 0.f;
    for (int c = tid; c < HD; c += 256) { float v = orow[c]; buf[c] = v; s += v; }
    red[tid] = s; __syncthreads();
    for (int off = 128; off; off >>= 1) { if (tid < off) red[tid] += red[tid + off]; __syncthreads(); }
    const float mean = red[0] * (1.f / HD);
    __syncthreads();

    float s2 = 0.f;
    for (int c = tid; c < HD; c += 256) { float d = buf[c] - mean; s2 += d * d; }
    red[tid] = s2; __syncthreads();
    for (int off = 128; off; off >>= 1) { if (tid < off) red[tid] += red[tid + off]; __syncthreads(); }
    const float rstd = rsqrtf(red[0] * (1.f / HD) + 1e-5f);

    for (int c = tid; c < HD; c += 256) {
        float v = ((buf[c] - mean) * rstd * lng[c] + lnb[c]) * urow[c];
        __half hv = __float2half(v);
        g_lnh[(size_t)row * HD + c] = hv;
        g_lnl[(size_t)row * HD + c] = __float2half(v - __half2float(hv));
    }
}

// ---------------------------------------------------------------------------
// launch
// ---------------------------------------------------------------------------
extern "C" void kernel_launch(void* const* d_in, const int* in_sizes, int n_in,
                              void* d_out, int out_size) {
    const float* x   = (const float*)d_in[0];
    const float* Wqk = (const float*)d_in[1];
    const float* bqk = (const float*)d_in[2];
    const float* Wv  = (const float*)d_in[3];
    const float* bv  = (const float*)d_in[4];
    const float* Wu  = (const float*)d_in[5];
    const float* bu  = (const float*)d_in[6];
    const float* Wo  = (const float*)d_in[7];
    const float* bo  = (const float*)d_in[8];
    const float* lng = (const float*)d_in[9];
    const float* lnb = (const float*)d_in[10];
    float* out = (float*)d_out;

    float *pu;
    __half *pxh, *pxl, *plnh, *plnl, *pwqk, *pwv, *pwu, *pwo, *pqh, *pql, *pvh;
    cudaGetSymbolAddress((void**)&pu, g_u);
    cudaGetSymbolAddress((void**)&pxh, g_xh);
    cudaGetSymbolAddress((void**)&pxl, g_xl);
    cudaGetSymbolAddress((void**)&plnh, g_lnh);
    cudaGetSymbolAddress((void**)&plnl, g_lnl);
    cudaGetSymbolAddress((void**)&pwqk, g_wqk);
    cudaGetSymbolAddress((void**)&pwv, g_wv);
    cudaGetSymbolAddress((void**)&pwu, g_wu);
    cudaGetSymbolAddress((void**)&pwo, g_wo);
    cudaGetSymbolAddress((void**)&pqh, g_qh);
    cudaGetSymbolAddress((void**)&pql, g_ql);
    cudaGetSymbolAddress((void**)&pvh, g_vh);

    cudaFuncSetAttribute(gemm_f16_2p, cudaFuncAttributeMaxDynamicSharedMemorySize, GEMM_SMEM);
    cudaFuncSetAttribute(kv_tc, cudaFuncAttributeMaxDynamicSharedMemorySize, KV_SMEM);
    cudaFuncSetAttribute(out_tc, cudaFuncAttributeMaxDynamicSharedMemorySize, OT_SMEM);

    // prep: split x; transpose 4 weights to fp16 in one launch
    {
        int n4 = MR * Ein / 4;
        split_kernel<<<(n4 + 255) / 256, 256>>>(x, pxh, pxl, n4);
        TsplitBatch T;
        T.W[0] = Wqk; T.T[0] = pwqk;
        T.W[1] = Wv;  T.T[1] = pwv;
        T.W[2] = Wu;  T.T[2] = pwu;
        T.W[3] = Wo;  T.T[3] = pwo;
        tsplit_kernel<<<dim3(64, 64, 4), dim3(32, 8)>>>(T);
    }

    // merged q/v/u GEMM: z=0 q(elu, half pair), z=1 v(silu, half), z=2 u(silu, fp32)
    {
        GemmBatch P;
        P.B[0] = pwqk; P.bias[0] = bqk; P.C[0] = nullptr; P.Ch[0] = pqh; P.Cl[0] = pql; P.mode[0] = 1; P.act[0] = 1;
        P.B[1] = pwv;  P.bias[1] = bv;  P.C[1] = nullptr; P.Ch[1] = pvh; P.Cl[1] = nullptr; P.mode[1] = 2; P.act[1] = 2;
        P.B[2] = pwu;  P.bias[2] = bu;  P.C[2] = pu;      P.Ch[2] = nullptr; P.Cl[2] = nullptr; P.mode[2] = 0; P.act[2] = 2;
        dim3 g3(HD / BN, MR / BM, 3);     // (16, 128, 3)
        gemm_f16_2p<<<g3, 256, GEMM_SMEM>>>(pxh, pxl, P);
    }

    // linear attention (tensor cores)
    kv_tc<<<dim3(Bn * HEADS, SPLITS), 256, KV_SMEM>>>();
    kvsum_kernel<<<(Bn * HEADS * DHd * DHd / 4 + 255) / 256, 256>>>();
    out_tc<<<dim3(MR / 128, HEADS), 256, OT_SMEM>>>();

    // LN * gate -> fp16 hi/lo
    ln_mul_kernel<<<MR, 256>>>(lng, lnb);

    // y = ln_out @ Wo + bo (fp32 out)
    {
        GemmBatch P;
        P.B[0] = pwo; P.bias[0] = bo; P.C[0] = out; P.Ch[0] = nullptr; P.Cl[0] = nullptr; P.mode[0] = 0; P.act[0] = 0;
        dim3 g1(HD / BN, MR / BM, 1);
        gemm_f16_2p<<<g1, 256, GEMM_SMEM>>>(plnh, plnl, P);
    }
}

// round 16
// speedup vs baseline: 3.2651x; 1.2726x over previous
#include <cuda_runtime.h>
#include <cuda_fp16.h>
#include <cstdint>
#include <math.h>

#define Bn    4
#define SEQ   4096
#define Ein   2048
#define HD    2048
#define HEADS 16
#define DHd   128
#define MR    (Bn * SEQ)      // 16384
#define SPLITS 4

// ---------------------------------------------------------------------------
// PTX helpers (base-target safe: sm_80+ instructions only)
// ---------------------------------------------------------------------------
__device__ __forceinline__ uint32_t smem_u32(const void* p) {
    uint32_t a;
    asm("{ .reg .u64 t; cvta.to.shared.u64 t, %1; cvt.u32.u64 %0, t; }" : "=r"(a) : "l"(p));
    return a;
}

#define CP16(dst, src) \
    asm volatile("cp.async.cg.shared.global [%0], [%1], 16;" :: "r"(dst), "l"(src) : "memory")
#define CP_COMMIT() asm volatile("cp.async.commit_group;" ::: "memory")
#define CP_WAIT(n)  asm volatile("cp.async.wait_group %0;" :: "n"(n) : "memory")

#define LDMX4(r, addr) \
    asm volatile("ldmatrix.sync.aligned.m8n8.x4.shared.b16 {%0,%1,%2,%3}, [%4];" \
        : "=r"((r)[0]), "=r"((r)[1]), "=r"((r)[2]), "=r"((r)[3]) : "r"(addr))

#define LDMX4T(r, addr) \
    asm volatile("ldmatrix.sync.aligned.m8n8.x4.trans.shared.b16 {%0,%1,%2,%3}, [%4];" \
        : "=r"((r)[0]), "=r"((r)[1]), "=r"((r)[2]), "=r"((r)[3]) : "r"(addr))

#define MMA_F16(d, a, b0v, b1v) \
    asm volatile("mma.sync.aligned.m16n8k16.row.col.f32.f16.f16.f32 " \
        "{%0,%1,%2,%3}, {%4,%5,%6,%7}, {%8,%9}, {%0,%1,%2,%3};" \
        : "+f"((d)[0]), "+f"((d)[1]), "+f"((d)[2]), "+f"((d)[3]) \
        : "r"((a)[0]), "r"((a)[1]), "r"((a)[2]), "r"((a)[3]), "r"(b0v), "r"(b1v))

// ---------------------------------------------------------------------------
// scratch (device globals; no allocation allowed)
// ---------------------------------------------------------------------------
__device__ float g_u [MR * HD];
__device__ float g_o [MR * HD];
__device__ float g_kv[SPLITS * Bn * HEADS * DHd * DHd];
__device__ __half g_kvh[Bn * HEADS * DHd * DHd];          // kv^T hi [bh][e][d]
__device__ __half g_kvl[Bn * HEADS * DHd * DHd];          // kv^T lo
__device__ __half g_qh [MR * HD], g_ql[MR * HD];          // elu(q) hi/lo
__device__ __half g_vh [MR * HD];                         // silu(v) fp16
__device__ __half g_xh [MR * Ein], g_xl[MR * Ein];
__device__ __half g_lnh[MR * HD], g_lnl[MR * HD];
__device__ __half g_wqk[HD * Ein];                        // [N][K] transposed fp16
__device__ __half g_wv [HD * Ein];
__device__ __half g_wu [HD * Ein];
__device__ __half g_wo [Ein * HD];

// ---------------------------------------------------------------------------
// batched fp16 GEMM: C[z] = act[z]( (Ah[+Al]) @ B[z]^T + bias[z] )
// nprod[z]==2 adds the Al product (A-side hi/lo compensation).
// BM=128 BN=128 BK=32, 3-stage cp.async ring, 8 warps (2m x 4n), warp 64x32.
// Output modes: 0 = fp32, 1 = fp16 hi/lo pair, 2 = fp16 single.
// CP_COMMIT every iteration (tail race fix, R14).
// ---------------------------------------------------------------------------
#define BM 128
#define BN 128
#define BK 32
#define STAGES 3
#define OFF_AH 0
#define OFF_AL 8192
#define OFF_B  16384
#define STG_BYTES 24576
#define GEMM_SMEM (STAGES * STG_BYTES)           // 73728
#define NIT (2048 / BK)                          // 64

struct GemmBatch {
    const __half* B[3];
    const float* bias[3];
    float* C[3];
    __half* Ch[3];
    __half* Cl[3];
    int mode[3];
    int act[3];      // 0 none, 1 elu, 2 silu
    int nprod[3];    // 1 or 2
};

__global__ void __launch_bounds__(256, 2) gemm_f16_2p(
    const __half* __restrict__ Ah, const __half* __restrict__ Al,
    GemmBatch P)
{
    extern __shared__ char smem[];
    const uint32_t sb = smem_u32(smem);
    const int tid = threadIdx.x;
    const int m0 = blockIdx.y * BM;
    const int n0 = blockIdx.x * BN;
    const int z  = blockIdx.z;
    const __half* __restrict__ Bp0 = P.B[z];
    const int nprod = P.nprod[z];

    const int lane = tid & 31, w = tid >> 5;
    const int wm = (w >> 2) * 64;
    const int wn = (w & 3) * 32;
    const int mi = lane >> 3, rowin = lane & 7;

    const int au = mi >> 1, aro = (mi & 1) << 3;
    uint32_t aoff[4]; int arx[4];
#pragma unroll
    for (int mt = 0; mt < 4; mt++) {
        int r = wm + mt * 16 + aro + rowin;
        aoff[mt] = r * 64;
        arx[mt] = (r >> 1) & 3;
    }
    const int bu = mi & 1, bro = (mi >> 1) << 3;
    uint32_t boff[2]; int brx[2];
#pragma unroll
    for (int p = 0; p < 2; p++) {
        int r = wn + p * 16 + bro + rowin;
        boff[p] = OFF_B + r * 64;
        brx[p] = (r >> 1) & 3;
    }

    const int lr = tid >> 2, lu = tid & 3;
    const uint32_t sw0 = (uint32_t)(lr * 64 + ((lu ^ ((lr >> 1) & 3)) << 4));
    const __half* Ahp = Ah + (size_t)(m0 + lr) * 2048 + lu * 8;
    const __half* Alp = Al + (size_t)(m0 + lr) * 2048 + lu * 8;
    const __half* Bpp = Bp0 + (size_t)(n0 + lr) * 2048 + lu * 8;

    float acc[4][4][4] = {};

#pragma unroll
    for (int s = 0; s < STAGES - 1; s++) {
        const uint32_t st = sb + s * STG_BYTES;
        const int k0 = s * BK;
        CP16(st + OFF_AH + sw0,        Ahp + k0);
        CP16(st + OFF_AH + sw0 + 4096, Ahp + k0 + (size_t)64 * 2048);
        if (nprod == 2) {
            CP16(st + OFF_AL + sw0,        Alp + k0);
            CP16(st + OFF_AL + sw0 + 4096, Alp + k0 + (size_t)64 * 2048);
        }
        CP16(st + OFF_B  + sw0,        Bpp + k0);
        CP16(st + OFF_B  + sw0 + 4096, Bpp + k0 + (size_t)64 * 2048);
        CP_COMMIT();
    }

    int cs = 0, ls = STAGES - 1;
    for (int it = 0; it < NIT; it++) {
        CP_WAIT(STAGES - 2);
        __syncthreads();

        const int nx = it + STAGES - 1;
        if (nx < NIT) {
            const uint32_t st2 = sb + ls * STG_BYTES;
            const int k0 = nx * BK;
            CP16(st2 + OFF_AH + sw0,        Ahp + k0);
            CP16(st2 + OFF_AH + sw0 + 4096, Ahp + k0 + (size_t)64 * 2048);
            if (nprod == 2) {
                CP16(st2 + OFF_AL + sw0,        Alp + k0);
                CP16(st2 + OFF_AL + sw0 + 4096, Alp + k0 + (size_t)64 * 2048);
            }
            CP16(st2 + OFF_B  + sw0,        Bpp + k0);
            CP16(st2 + OFF_B  + sw0 + 4096, Bpp + k0 + (size_t)64 * 2048);
        }
        CP_COMMIT();   // unconditional: keeps group-count arithmetic valid in tail

        const uint32_t st = sb + cs * STG_BYTES;
#pragma unroll
        for (int ks = 0; ks < 2; ks++) {
            uint32_t bb[2][4];
#pragma unroll
            for (int p = 0; p < 2; p++)
                LDMX4(bb[p], st + boff[p] + (uint32_t)(((2 * ks + bu) ^ brx[p]) << 4));
            uint32_t ah[4][4];
#pragma unroll
            for (int mt = 0; mt < 4; mt++)
                LDMX4(ah[mt], st + OFF_AH + aoff[mt] + (uint32_t)(((2 * ks + au) ^ arx[mt]) << 4));
#pragma unroll
            for (int mt = 0; mt < 4; mt++)
#pragma unroll
                for (int nt = 0; nt < 4; nt++)
                    MMA_F16(acc[mt][nt], ah[mt], bb[nt >> 1][(nt & 1) * 2], bb[nt >> 1][(nt & 1) * 2 + 1]);
            if (nprod == 2) {
#pragma unroll
                for (int mt = 0; mt < 4; mt++)
                    LDMX4(ah[mt], st + OFF_AL + aoff[mt] + (uint32_t)(((2 * ks + au) ^ arx[mt]) << 4));
#pragma unroll
                for (int mt = 0; mt < 4; mt++)
#pragma unroll
                    for (int nt = 0; nt < 4; nt++)
                        MMA_F16(acc[mt][nt], ah[mt], bb[nt >> 1][(nt & 1) * 2], bb[nt >> 1][(nt & 1) * 2 + 1]);
            }
        }
        if (++cs == STAGES) cs = 0;
        if (++ls == STAGES) ls = 0;
    }

    // -------- epilogue --------
    const float* __restrict__ bias = P.bias[z];
    const int act = P.act[z];
    const int mode = P.mode[z];
    const int g = lane >> 2, t = lane & 3;
#pragma unroll
    for (int mt = 0; mt < 4; mt++) {
#pragma unroll
        for (int nt = 0; nt < 4; nt++) {
            const int rm = m0 + wm + mt * 16 + g;
            const int cn = n0 + wn + nt * 8 + 2 * t;
            const float b0 = bias[cn], b1 = bias[cn + 1];
            float v0 = acc[mt][nt][0] + b0;
            float v1 = acc[mt][nt][1] + b1;
            float v2 = acc[mt][nt][2] + b0;
            float v3 = acc[mt][nt][3] + b1;
            if (act == 1) {
                v0 = v0 > 0.f ? v0 : (expf(v0) - 1.f);
                v1 = v1 > 0.f ? v1 : (expf(v1) - 1.f);
                v2 = v2 > 0.f ? v2 : (expf(v2) - 1.f);
                v3 = v3 > 0.f ? v3 : (expf(v3) - 1.f);
            } else if (act == 2) {
                v0 = v0 / (1.f + expf(-v0));
                v1 = v1 / (1.f + expf(-v1));
                v2 = v2 / (1.f + expf(-v2));
                v3 = v3 / (1.f + expf(-v3));
            }
            if (mode == 0) {
                float* C = P.C[z];
                *(float2*)(C + (size_t)rm * 2048 + cn) = make_float2(v0, v1);
                *(float2*)(C + (size_t)(rm + 8) * 2048 + cn) = make_float2(v2, v3);
            } else {
                __half* Ch = P.Ch[z];
                __half h0 = __float2half(v0), h1 = __float2half(v1);
                __half h2 = __float2half(v2), h3 = __float2half(v3);
                *(__half2*)(Ch + (size_t)rm * 2048 + cn) = __halves2half2(h0, h1);
                *(__half2*)(Ch + (size_t)(rm + 8) * 2048 + cn) = __halves2half2(h2, h3);
                if (mode == 1) {
                    __half* Cl = P.Cl[z];
                    *(__half2*)(Cl + (size_t)rm * 2048 + cn) =
                        __halves2half2(__float2half(v0 - __half2float(h0)),
                                       __float2half(v1 - __half2float(h1)));
                    *(__half2*)(Cl + (size_t)(rm + 8) * 2048 + cn) =
                        __halves2half2(__float2half(v2 - __half2float(h2)),
                                       __float2half(v3 - __half2float(h3)));
                }
            }
        }
    }
}

// ---------------------------------------------------------------------------
// kv_tc: kvT[bh][e][d] slice = V^T (Qh+Ql) over one seq split, tensor cores.
// A = vh (m=e, trans-ldmatrix), B = qh/ql (n=d, trans-ldmatrix), K = seq.
// Unconditional-commit tail fix.
// ---------------------------------------------------------------------------
#define KV_OQH 0
#define KV_OQL 8192
#define KV_OVH 16384
#define KV_STGB 24576
#define KV_SMEM (3 * KV_STGB)     // 73728

__global__ void __launch_bounds__(256, 2) kv_tc() {
    extern __shared__ char smem[];
    const uint32_t sb = smem_u32(smem);
    const int tid = threadIdx.x;
    const int bh = blockIdx.x;
    const int b = bh >> 4, h = bh & 15;
    const int seq0 = blockIdx.y * (SEQ / SPLITS);   // 1024-chunk
    const int lane = tid & 31, w = tid >> 5;
    const int wm = (w >> 2) * 64;      // e
    const int wn = (w & 3) * 32;       // d
    const int mi = lane >> 3, rowin = lane & 7;

    const int rowA = ((mi >> 1) << 3) + rowin;
    const int rowB = ((mi & 1) << 3) + rowin;
    uint32_t cA[4], cB[2];
#pragma unroll
    for (int mt = 0; mt < 4; mt++)
        cA[mt] = (uint32_t)((((wm + mt * 16 + ((mi & 1) << 3)) >> 3) ^ rowin) << 4);
#pragma unroll
    for (int p = 0; p < 2; p++)
        cB[p] = (uint32_t)((((wn + p * 16 + ((mi >> 1) << 3)) >> 3) ^ rowin) << 4);

    const int lr = tid >> 3, lc = tid & 7;
    const uint32_t dA = (uint32_t)(lr * 256 + ((lc ^ (lr & 7)) << 4));
    const uint32_t dB = (uint32_t)(lr * 256 + (((lc + 8) ^ (lr & 7)) << 4));
    const size_t g0 = (size_t)(b * SEQ + seq0 + lr) * 2048 + h * 128;

    float acc[4][4][4] = {};

#pragma unroll
    for (int s = 0; s < 2; s++) {
        const uint32_t st = sb + s * KV_STGB;
        const size_t go = g0 + (size_t)(s * 32) * 2048;
        CP16(st + KV_OQH + dA, g_qh + go + lc * 8);
        CP16(st + KV_OQH + dB, g_qh + go + (lc + 8) * 8);
        CP16(st + KV_OQL + dA, g_ql + go + lc * 8);
        CP16(st + KV_OQL + dB, g_ql + go + (lc + 8) * 8);
        CP16(st + KV_OVH + dA, g_vh + go + lc * 8);
        CP16(st + KV_OVH + dB, g_vh + go + (lc + 8) * 8);
        CP_COMMIT();
    }

    int cs = 0, ls = 2;
    for (int it = 0; it < 32; it++) {
        CP_WAIT(1);
        __syncthreads();
        const int nx = it + 2;
        if (nx < 32) {
            const uint32_t st2 = sb + ls * KV_STGB;
            const size_t go = g0 + (size_t)(nx * 32) * 2048;
            CP16(st2 + KV_OQH + dA, g_qh + go + lc * 8);
            CP16(st2 + KV_OQH + dB, g_qh + go + (lc + 8) * 8);
            CP16(st2 + KV_OQL + dA, g_ql + go + lc * 8);
            CP16(st2 + KV_OQL + dB, g_ql + go + (lc + 8) * 8);
            CP16(st2 + KV_OVH + dA, g_vh + go + lc * 8);
            CP16(st2 + KV_OVH + dB, g_vh + go + (lc + 8) * 8);
        }
        CP_COMMIT();   // unconditional (tail race fix)
        const uint32_t st = sb + cs * KV_STGB;
#pragma unroll
        for (int ks = 0; ks < 2; ks++) {
            uint32_t av[4][4];
#pragma unroll
            for (int mt = 0; mt < 4; mt++)
                LDMX4T(av[mt], st + KV_OVH + (uint32_t)((ks * 16 + rowA) * 256) + cA[mt]);
            uint32_t bq[2][4];
#pragma unroll
            for (int p = 0; p < 2; p++)
                LDMX4T(bq[p], st + KV_OQH + (uint32_t)((ks * 16 + rowB) * 256) + cB[p]);
#pragma unroll
            for (int mt = 0; mt < 4; mt++)
#pragma unroll
                for (int nt = 0; nt < 4; nt++)
                    MMA_F16(acc[mt][nt], av[mt], bq[nt >> 1][(nt & 1) * 2], bq[nt >> 1][(nt & 1) * 2 + 1]);
#pragma unroll
            for (int p = 0; p < 2; p++)
                LDMX4T(bq[p], st + KV_OQL + (uint32_t)((ks * 16 + rowB) * 256) + cB[p]);
#pragma unroll
            for (int mt = 0; mt < 4; mt++)
#pragma unroll
                for (int nt = 0; nt < 4; nt++)
                    MMA_F16(acc[mt][nt], av[mt], bq[nt >> 1][(nt & 1) * 2], bq[nt >> 1][(nt & 1) * 2 + 1]);
        }
        if (++cs == 3) cs = 0;
        if (++ls == 3) ls = 0;
    }

    float* kvp = g_kv + ((size_t)blockIdx.y * Bn * HEADS + bh) * DHd * DHd;
    const int g = lane >> 2, t = lane & 3;
#pragma unroll
    for (int mt = 0; mt < 4; mt++)
#pragma unroll
        for (int nt = 0; nt < 4; nt++) {
            const int rm = wm + mt * 16 + g;
            const int cn = wn + nt * 8 + 2 * t;
            *(float2*)(kvp + rm * 128 + cn) = make_float2(acc[mt][nt][0], acc[mt][nt][1]);
            *(float2*)(kvp + (rm + 8) * 128 + cn) = make_float2(acc[mt][nt][2], acc[mt][nt][3]);
        }
}

// ---------------------------------------------------------------------------
// kvsum: sum SPLITS fp32 slices -> fp16 hi/lo pair
// ---------------------------------------------------------------------------
__global__ void kvsum_kernel() {
    const int n4 = Bn * HEADS * DHd * DHd / 4;      // 262144
    int i = blockIdx.x * blockDim.x + threadIdx.x;
    if (i >= n4) return;
    const float4* src = (const float4*)g_kv;
    float4 s = src[i];
#pragma unroll
    for (int sp = 1; sp < SPLITS; sp++) {
        float4 t = src[i + (size_t)sp * n4];
        s.x += t.x; s.y += t.y; s.z += t.z; s.w += t.w;
    }
    __half h0 = __float2half(s.x), h1 = __float2half(s.y);
    __half h2 = __float2half(s.z), h3 = __float2half(s.w);
    __half2* dh = (__half2*)g_kvh;
    __half2* dl = (__half2*)g_kvl;
    dh[i * 2 + 0] = __halves2half2(h0, h1);
    dh[i * 2 + 1] = __halves2half2(h2, h3);
    dl[i * 2 + 0] = __halves2half2(__float2half(s.x - __half2float(h0)),
                                   __float2half(s.y - __half2float(h1)));
    dl[i * 2 + 1] = __halves2half2(__float2half(s.z - __half2float(h2)),
                                   __float2half(s.w - __half2float(h3)));
}

// ---------------------------------------------------------------------------
// out_tc: o[m][e] = (Qh+Ql)[m][d] @ (Kh+Kl)T[e][d]  (3-product, drop QlKl).
// Monolithic 128KB smem (qh|ql|kvh|kvl of 32KB), K=128, 8 k-iters. 1 CTA/SM.
// ---------------------------------------------------------------------------
#define OT_OQH 0
#define OT_OQL 32768
#define OT_OKH 65536
#define OT_OKL 98304
#define OT_SMEM 131072

__global__ void __launch_bounds__(256) out_tc() {
    extern __shared__ char smem[];
    const uint32_t sb = smem_u32(smem);
    const int tid = threadIdx.x;
    const int m0 = blockIdx.x * 128;
    const int h = blockIdx.y;
    const int b = m0 >> 12;
    const int lane = tid & 31, w = tid >> 5;
    const int wm = (w >> 2) * 64;
    const int wn = (w & 3) * 32;
    const int mi = lane >> 3, rowin = lane & 7;

#pragma unroll
    for (int i = 0; i < 8; i++) {
        const int widx = tid + i * 256;
        const int row = widx >> 4, c = widx & 15;
        const uint32_t dst = (uint32_t)(row * 256 + ((c ^ (row & 7)) << 4));
        CP16(sb + OT_OQH + dst, g_qh + (size_t)(m0 + row) * 2048 + h * 128 + c * 8);
        CP16(sb + OT_OQL + dst, g_ql + (size_t)(m0 + row) * 2048 + h * 128 + c * 8);
        CP16(sb + OT_OKH + dst, g_kvh + (size_t)(b * HEADS + h) * 16384 + row * 128 + c * 8);
        CP16(sb + OT_OKL + dst, g_kvl + (size_t)(b * HEADS + h) * 16384 + row * 128 + c * 8);
    }
    CP_COMMIT();
    CP_WAIT(0);
    __syncthreads();

    const int arow_ = ((mi & 1) << 3) + rowin;
    const int akc = mi >> 1;
    const int brow_ = ((mi >> 1) << 3) + rowin;
    const int bkc = mi & 1;

    float acc[4][4][4] = {};
#pragma unroll
    for (int kt = 0; kt < 8; kt++) {
        uint32_t bb[2][4];
#pragma unroll
        for (int p = 0; p < 2; p++) {
            const int row = wn + p * 16 + brow_;
            LDMX4(bb[p], sb + OT_OKH + (uint32_t)(row * 256) + (uint32_t)(((kt * 2 + bkc) ^ rowin) << 4));
        }
        uint32_t ahh[4][4];
#pragma unroll
        for (int mt = 0; mt < 4; mt++) {
            const int row = wm + mt * 16 + arow_;
            LDMX4(ahh[mt], sb + OT_OQH + (uint32_t)(row * 256) + (uint32_t)(((kt * 2 + akc) ^ rowin) << 4));
        }
        // Qh * Kh
#pragma unroll
        for (int mt = 0; mt < 4; mt++)
#pragma unroll
            for (int nt = 0; nt < 4; nt++)
                MMA_F16(acc[mt][nt], ahh[mt], bb[nt >> 1][(nt & 1) * 2], bb[nt >> 1][(nt & 1) * 2 + 1]);
        // Ql * Kh
        {
            uint32_t ahl[4][4];
#pragma unroll
            for (int mt = 0; mt < 4; mt++) {
                const int row = wm + mt * 16 + arow_;
                LDMX4(ahl[mt], sb + OT_OQL + (uint32_t)(row * 256) + (uint32_t)(((kt * 2 + akc) ^ rowin) << 4));
            }
#pragma unroll
            for (int mt = 0; mt < 4; mt++)
#pragma unroll
                for (int nt = 0; nt < 4; nt++)
                    MMA_F16(acc[mt][nt], ahl[mt], bb[nt >> 1][(nt & 1) * 2], bb[nt >> 1][(nt & 1) * 2 + 1]);
        }
        // Qh * Kl (reuse bb)
#pragma unroll
        for (int p = 0; p < 2; p++) {
            const int row = wn + p * 16 + brow_;
            LDMX4(bb[p], sb + OT_OKL + (uint32_t)(row * 256) + (uint32_t)(((kt * 2 + bkc) ^ rowin) << 4));
        }
#pragma unroll
        for (int mt = 0; mt < 4; mt++)
#pragma unroll
            for (int nt = 0; nt < 4; nt++)
                MMA_F16(acc[mt][nt], ahh[mt], bb[nt >> 1][(nt & 1) * 2], bb[nt >> 1][(nt & 1) * 2 + 1]);
    }

    const int g = lane >> 2, t = lane & 3;
#pragma unroll
    for (int mt = 0; mt < 4; mt++)
#pragma unroll
        for (int nt = 0; nt < 4; nt++) {
            const int rm = m0 + wm + mt * 16 + g;
            const int cn = h * 128 + wn + nt * 8 + 2 * t;
            *(float2*)(g_o + (size_t)rm * 2048 + cn) = make_float2(acc[mt][nt][0], acc[mt][nt][1]);
            *(float2*)(g_o + (size_t)(rm + 8) * 2048 + cn) = make_float2(acc[mt][nt][2], acc[mt][nt][3]);
        }
}

// ---------------------------------------------------------------------------
// prep kernels
// ---------------------------------------------------------------------------
__global__ void split_kernel(const float* __restrict__ x,
                             __half* __restrict__ h, __half* __restrict__ l, int n4) {
    int i = blockIdx.x * blockDim.x + threadIdx.x;
    if (i >= n4) return;
    float4 v = ((const float4*)x)[i];
    __half h0 = __float2half(v.x), h1 = __float2half(v.y);
    __half h2 = __float2half(v.z), h3 = __float2half(v.w);
    __half2* hp = (__half2*)h;
    __half2* lp = (__half2*)l;
    hp[i * 2 + 0] = __halves2half2(h0, h1);
    hp[i * 2 + 1] = __halves2half2(h2, h3);
    lp[i * 2 + 0] = __halves2half2(__float2half(v.x - __half2float(h0)),
                                   __float2half(v.y - __half2float(h1)));
    lp[i * 2 + 1] = __halves2half2(__float2half(v.z - __half2float(h2)),
                                   __float2half(v.w - __half2float(h3)));
}

struct TsplitBatch {
    const float* W[4];
    __half* T[4];
};
__global__ void tsplit_kernel(TsplitBatch P) {
    __shared__ float tile[32][33];
    const float* __restrict__ W = P.W[blockIdx.z];
    __half* __restrict__ T = P.T[blockIdx.z];
    const int k0 = blockIdx.y * 32, n0 = blockIdx.x * 32;
    const int tx = threadIdx.x, ty = threadIdx.y;
#pragma unroll
    for (int i = 0; i < 32; i += 8)
        tile[ty + i][tx] = W[(size_t)(k0 + ty + i) * 2048 + n0 + tx];
    __syncthreads();
#pragma unroll
    for (int i = 0; i < 32; i += 8)
        T[(size_t)(n0 + ty + i) * 2048 + k0 + tx] = __float2half(tile[tx][ty + i]);
}

// ---------------------------------------------------------------------------
// LayerNorm over HD, * gate u, emit fp16 hi/lo for final GEMM
// ---------------------------------------------------------------------------
__global__ void ln_mul_kernel(const float* __restrict__ lng, const float* __restrict__ lnb) {
    __shared__ float buf[HD];
    __shared__ float red[256];
    const int row = blockIdx.x;
    const int tid = threadIdx.x;
    const float* orow = g_o + (size_t)row * HD;
    const float* urow = g_u + (size_t)row * HD;

    float s = 0.f;
    for (int c = tid; c < HD; c += 256) { float v = orow[c]; buf[c] = v; s += v; }
    red[tid] = s; __syncthreads();
    for (int off = 128; off; off >>= 1) { if (tid < off) red[tid] += red[tid + off]; __syncthreads(); }
    const float mean = red[0] * (1.f / HD);
    __syncthreads();

    float s2 = 0.f;
    for (int c = tid; c < HD; c += 256) { float d = buf[c] - mean; s2 += d * d; }
    red[tid] = s2; __syncthreads();
    for (int off = 128; off; off >>= 1) { if (tid < off) red[tid] += red[tid + off]; __syncthreads(); }
    const float rstd = rsqrtf(red[0] * (1.f / HD) + 1e-5f);

    for (int c = tid; c < HD; c += 256) {
        float v = ((buf[c] - mean) * rstd * lng[c] + lnb[c]) * urow[c];
        __half hv = __float2half(v);
        g_lnh[(size_t)row * HD + c] = hv;
        g_lnl[(size_t)row * HD + c] = __float2half(v - __half2float(hv));
    }
}

// ---------------------------------------------------------------------------
// launch
// ---------------------------------------------------------------------------
extern "C" void kernel_launch(void* const* d_in, const int* in_sizes, int n_in,
                              void* d_out, int out_size) {
    const float* x   = (const float*)d_in[0];
    const float* Wqk = (const float*)d_in[1];
    const float* bqk = (const float*)d_in[2];
    const float* Wv  = (const float*)d_in[3];
    const float* bv  = (const float*)d_in[4];
    const float* Wu  = (const float*)d_in[5];
    const float* bu  = (const float*)d_in[6];
    const float* Wo  = (const float*)d_in[7];
    const float* bo  = (const float*)d_in[8];
    const float* lng = (const float*)d_in[9];
    const float* lnb = (const float*)d_in[10];
    float* out = (float*)d_out;

    float *pu;
    __half *pxh, *pxl, *plnh, *plnl, *pwqk, *pwv, *pwu, *pwo, *pqh, *pql, *pvh;
    cudaGetSymbolAddress((void**)&pu, g_u);
    cudaGetSymbolAddress((void**)&pxh, g_xh);
    cudaGetSymbolAddress((void**)&pxl, g_xl);
    cudaGetSymbolAddress((void**)&plnh, g_lnh);
    cudaGetSymbolAddress((void**)&plnl, g_lnl);
    cudaGetSymbolAddress((void**)&pwqk, g_wqk);
    cudaGetSymbolAddress((void**)&pwv, g_wv);
    cudaGetSymbolAddress((void**)&pwu, g_wu);
    cudaGetSymbolAddress((void**)&pwo, g_wo);
    cudaGetSymbolAddress((void**)&pqh, g_qh);
    cudaGetSymbolAddress((void**)&pql, g_ql);
    cudaGetSymbolAddress((void**)&pvh, g_vh);

    cudaFuncSetAttribute(gemm_f16_2p, cudaFuncAttributeMaxDynamicSharedMemorySize, GEMM_SMEM);
    cudaFuncSetAttribute(kv_tc, cudaFuncAttributeMaxDynamicSharedMemorySize, KV_SMEM);
    cudaFuncSetAttribute(out_tc, cudaFuncAttributeMaxDynamicSharedMemorySize, OT_SMEM);

    // prep: split x; transpose 4 weights to fp16 in one launch
    {
        int n4 = MR * Ein / 4;
        split_kernel<<<(n4 + 255) / 256, 256>>>(x, pxh, pxl, n4);
        TsplitBatch T;
        T.W[0] = Wqk; T.T[0] = pwqk;
        T.W[1] = Wv;  T.T[1] = pwv;
        T.W[2] = Wu;  T.T[2] = pwu;
        T.W[3] = Wo;  T.T[3] = pwo;
        tsplit_kernel<<<dim3(64, 64, 4), dim3(32, 8)>>>(T);
    }

    // merged q/v/u GEMM: q(elu, pair, 2-prod), v(silu, half, 1-prod), u(silu, fp32, 1-prod)
    {
        GemmBatch P;
        P.B[0] = pwqk; P.bias[0] = bqk; P.C[0] = nullptr; P.Ch[0] = pqh; P.Cl[0] = pql; P.mode[0] = 1; P.act[0] = 1; P.nprod[0] = 2;
        P.B[1] = pwv;  P.bias[1] = bv;  P.C[1] = nullptr; P.Ch[1] = pvh; P.Cl[1] = nullptr; P.mode[1] = 2; P.act[1] = 2; P.nprod[1] = 1;
        P.B[2] = pwu;  P.bias[2] = bu;  P.C[2] = pu;      P.Ch[2] = nullptr; P.Cl[2] = nullptr; P.mode[2] = 0; P.act[2] = 2; P.nprod[2] = 1;
        dim3 g3(HD / BN, MR / BM, 3);     // (16, 128, 3)
        gemm_f16_2p<<<g3, 256, GEMM_SMEM>>>(pxh, pxl, P);
    }

    // linear attention (tensor cores)
    kv_tc<<<dim3(Bn * HEADS, SPLITS), 256, KV_SMEM>>>();
    kvsum_kernel<<<(Bn * HEADS * DHd * DHd / 4 + 255) / 256, 256>>>();
    out_tc<<<dim3(MR / 128, HEADS), 256, OT_SMEM>>>();

    // LN * gate -> fp16 hi/lo
    ln_mul_kernel<<<MR, 256>>>(lng, lnb);

    // y = ln_out @ Wo + bo (fp32 out, 2-prod)
    {
        GemmBatch P;
        P.B[0] = pwo; P.bias[0] = bo; P.C[0] = out; P.Ch[0] = nullptr; P.Cl[0] = nullptr; P.mode[0] = 0; P.act[0] = 0; P.nprod[0] = 2;
        dim3 g1(HD / BN, MR / BM, 1);
        gemm_f16_2p<<<g1, 256, GEMM_SMEM>>>(plnh, plnl, P);
    }
}

// round 17
// speedup vs baseline: 3.6911x; 1.1305x over previous
#include <cuda_runtime.h>
#include <cuda_fp16.h>
#include <cstdint>
#include <math.h>

#define Bn    4
#define SEQ   4096
#define Ein   2048
#define HD    2048
#define HEADS 16
#define DHd   128
#define MR    (Bn * SEQ)      // 16384
#define SPLITS 4

// ---------------------------------------------------------------------------
// PTX helpers (base-target safe: sm_80+ instructions only)
// ---------------------------------------------------------------------------
__device__ __forceinline__ uint32_t smem_u32(const void* p) {
    uint32_t a;
    asm("{ .reg .u64 t; cvta.to.shared.u64 t, %1; cvt.u32.u64 %0, t; }" : "=r"(a) : "l"(p));
    return a;
}

#define CP16(dst, src) \
    asm volatile("cp.async.cg.shared.global [%0], [%1], 16;" :: "r"(dst), "l"(src) : "memory")
#define CP_COMMIT() asm volatile("cp.async.commit_group;" ::: "memory")
#define CP_WAIT(n)  asm volatile("cp.async.wait_group %0;" :: "n"(n) : "memory")

#define LDMX4(r, addr) \
    asm volatile("ldmatrix.sync.aligned.m8n8.x4.shared.b16 {%0,%1,%2,%3}, [%4];" \
        : "=r"((r)[0]), "=r"((r)[1]), "=r"((r)[2]), "=r"((r)[3]) : "r"(addr))

#define LDMX4T(r, addr) \
    asm volatile("ldmatrix.sync.aligned.m8n8.x4.trans.shared.b16 {%0,%1,%2,%3}, [%4];" \
        : "=r"((r)[0]), "=r"((r)[1]), "=r"((r)[2]), "=r"((r)[3]) : "r"(addr))

#define MMA_F16(d, a, b0v, b1v) \
    asm volatile("mma.sync.aligned.m16n8k16.row.col.f32.f16.f16.f32 " \
        "{%0,%1,%2,%3}, {%4,%5,%6,%7}, {%8,%9}, {%0,%1,%2,%3};" \
        : "+f"((d)[0]), "+f"((d)[1]), "+f"((d)[2]), "+f"((d)[3]) \
        : "r"((a)[0]), "r"((a)[1]), "r"((a)[2]), "r"((a)[3]), "r"(b0v), "r"(b1v))

// ---------------------------------------------------------------------------
// scratch (device globals; no allocation allowed)
// ---------------------------------------------------------------------------
__device__ float g_u [MR * HD];
__device__ float g_o [MR * HD];
__device__ float g_kv[SPLITS * Bn * HEADS * DHd * DHd];
__device__ __half g_kvh[Bn * HEADS * DHd * DHd];          // kv^T hi [bh][e][d]
__device__ __half g_kvl[Bn * HEADS * DHd * DHd];          // kv^T lo
__device__ __half g_qh [MR * HD], g_ql[MR * HD];          // elu(q) hi/lo
__device__ __half g_vh [MR * HD];                         // silu(v) fp16
__device__ __half g_xh [MR * Ein], g_xl[MR * Ein];
__device__ __half g_lnh[MR * HD];
__device__ __half g_wqk[HD * Ein];                        // [N][K] transposed fp16
__device__ __half g_wv [HD * Ein];
__device__ __half g_wu [HD * Ein];
__device__ __half g_wo [Ein * HD];

// ---------------------------------------------------------------------------
// batched fp16 GEMM: C[z] = act[z]( (Ah[+Al]) @ B[z]^T + bias[z] )
// nprod[z]==2 adds the Al product (A-side hi/lo compensation).
// BM=128 BN=128 BK=32, 3-stage cp.async ring, 8 warps (2m x 4n), warp 64x32.
// Output modes: 0 = fp32, 1 = fp16 hi/lo pair, 2 = fp16 single.
// CP_COMMIT every iteration (tail race fix, R14).
// ---------------------------------------------------------------------------
#define BM 128
#define BN 128
#define BK 32
#define STAGES 3
#define OFF_AH 0
#define OFF_AL 8192
#define OFF_B  16384
#define STG_BYTES 24576
#define GEMM_SMEM (STAGES * STG_BYTES)           // 73728
#define NIT (2048 / BK)                          // 64

struct GemmBatch {
    const __half* B[3];
    const float* bias[3];
    float* C[3];
    __half* Ch[3];
    __half* Cl[3];
    int mode[3];
    int act[3];      // 0 none, 1 elu, 2 silu
    int nprod[3];    // 1 or 2
};

__global__ void __launch_bounds__(256, 2) gemm_f16_2p(
    const __half* __restrict__ Ah, const __half* __restrict__ Al,
    GemmBatch P)
{
    extern __shared__ char smem[];
    const uint32_t sb = smem_u32(smem);
    const int tid = threadIdx.x;
    const int m0 = blockIdx.y * BM;
    const int n0 = blockIdx.x * BN;
    const int z  = blockIdx.z;
    const __half* __restrict__ Bp0 = P.B[z];
    const int nprod = P.nprod[z];

    const int lane = tid & 31, w = tid >> 5;
    const int wm = (w >> 2) * 64;
    const int wn = (w & 3) * 32;
    const int mi = lane >> 3, rowin = lane & 7;

    const int au = mi >> 1, aro = (mi & 1) << 3;
    uint32_t aoff[4]; int arx[4];
#pragma unroll
    for (int mt = 0; mt < 4; mt++) {
        int r = wm + mt * 16 + aro + rowin;
        aoff[mt] = r * 64;
        arx[mt] = (r >> 1) & 3;
    }
    const int bu = mi & 1, bro = (mi >> 1) << 3;
    uint32_t boff[2]; int brx[2];
#pragma unroll
    for (int p = 0; p < 2; p++) {
        int r = wn + p * 16 + bro + rowin;
        boff[p] = OFF_B + r * 64;
        brx[p] = (r >> 1) & 3;
    }

    const int lr = tid >> 2, lu = tid & 3;
    const uint32_t sw0 = (uint32_t)(lr * 64 + ((lu ^ ((lr >> 1) & 3)) << 4));
    const __half* Ahp = Ah + (size_t)(m0 + lr) * 2048 + lu * 8;
    const __half* Alp = Al + (size_t)(m0 + lr) * 2048 + lu * 8;
    const __half* Bpp = Bp0 + (size_t)(n0 + lr) * 2048 + lu * 8;

    float acc[4][4][4] = {};

#pragma unroll
    for (int s = 0; s < STAGES - 1; s++) {
        const uint32_t st = sb + s * STG_BYTES;
        const int k0 = s * BK;
        CP16(st + OFF_AH + sw0,        Ahp + k0);
        CP16(st + OFF_AH + sw0 + 4096, Ahp + k0 + (size_t)64 * 2048);
        if (nprod == 2) {
            CP16(st + OFF_AL + sw0,        Alp + k0);
            CP16(st + OFF_AL + sw0 + 4096, Alp + k0 + (size_t)64 * 2048);
        }
        CP16(st + OFF_B  + sw0,        Bpp + k0);
        CP16(st + OFF_B  + sw0 + 4096, Bpp + k0 + (size_t)64 * 2048);
        CP_COMMIT();
    }

    int cs = 0, ls = STAGES - 1;
    for (int it = 0; it < NIT; it++) {
        CP_WAIT(STAGES - 2);
        __syncthreads();

        const int nx = it + STAGES - 1;
        if (nx < NIT) {
            const uint32_t st2 = sb + ls * STG_BYTES;
            const int k0 = nx * BK;
            CP16(st2 + OFF_AH + sw0,        Ahp + k0);
            CP16(st2 + OFF_AH + sw0 + 4096, Ahp + k0 + (size_t)64 * 2048);
            if (nprod == 2) {
                CP16(st2 + OFF_AL + sw0,        Alp + k0);
                CP16(st2 + OFF_AL + sw0 + 4096, Alp + k0 + (size_t)64 * 2048);
            }
            CP16(st2 + OFF_B  + sw0,        Bpp + k0);
            CP16(st2 + OFF_B  + sw0 + 4096, Bpp + k0 + (size_t)64 * 2048);
        }
        CP_COMMIT();   // unconditional: keeps group-count arithmetic valid in tail

        const uint32_t st = sb + cs * STG_BYTES;
#pragma unroll
        for (int ks = 0; ks < 2; ks++) {
            uint32_t bb[2][4];
#pragma unroll
            for (int p = 0; p < 2; p++)
                LDMX4(bb[p], st + boff[p] + (uint32_t)(((2 * ks + bu) ^ brx[p]) << 4));
            uint32_t ah[4][4];
#pragma unroll
            for (int mt = 0; mt < 4; mt++)
                LDMX4(ah[mt], st + OFF_AH + aoff[mt] + (uint32_t)(((2 * ks + au) ^ arx[mt]) << 4));
#pragma unroll
            for (int mt = 0; mt < 4; mt++)
#pragma unroll
                for (int nt = 0; nt < 4; nt++)
                    MMA_F16(acc[mt][nt], ah[mt], bb[nt >> 1][(nt & 1) * 2], bb[nt >> 1][(nt & 1) * 2 + 1]);
            if (nprod == 2) {
#pragma unroll
                for (int mt = 0; mt < 4; mt++)
                    LDMX4(ah[mt], st + OFF_AL + aoff[mt] + (uint32_t)(((2 * ks + au) ^ arx[mt]) << 4));
#pragma unroll
                for (int mt = 0; mt < 4; mt++)
#pragma unroll
                    for (int nt = 0; nt < 4; nt++)
                        MMA_F16(acc[mt][nt], ah[mt], bb[nt >> 1][(nt & 1) * 2], bb[nt >> 1][(nt & 1) * 2 + 1]);
            }
        }
        if (++cs == STAGES) cs = 0;
        if (++ls == STAGES) ls = 0;
    }

    // -------- epilogue --------
    const float* __restrict__ bias = P.bias[z];
    const int act = P.act[z];
    const int mode = P.mode[z];
    const int g = lane >> 2, t = lane & 3;
#pragma unroll
    for (int mt = 0; mt < 4; mt++) {
#pragma unroll
        for (int nt = 0; nt < 4; nt++) {
            const int rm = m0 + wm + mt * 16 + g;
            const int cn = n0 + wn + nt * 8 + 2 * t;
            const float b0 = bias[cn], b1 = bias[cn + 1];
            float v0 = acc[mt][nt][0] + b0;
            float v1 = acc[mt][nt][1] + b1;
            float v2 = acc[mt][nt][2] + b0;
            float v3 = acc[mt][nt][3] + b1;
            if (act == 1) {
                v0 = v0 > 0.f ? v0 : (expf(v0) - 1.f);
                v1 = v1 > 0.f ? v1 : (expf(v1) - 1.f);
                v2 = v2 > 0.f ? v2 : (expf(v2) - 1.f);
                v3 = v3 > 0.f ? v3 : (expf(v3) - 1.f);
            } else if (act == 2) {
                v0 = v0 / (1.f + expf(-v0));
                v1 = v1 / (1.f + expf(-v1));
                v2 = v2 / (1.f + expf(-v2));
                v3 = v3 / (1.f + expf(-v3));
            }
            if (mode == 0) {
                float* C = P.C[z];
                *(float2*)(C + (size_t)rm * 2048 + cn) = make_float2(v0, v1);
                *(float2*)(C + (size_t)(rm + 8) * 2048 + cn) = make_float2(v2, v3);
            } else {
                __half* Ch = P.Ch[z];
                __half h0 = __float2half(v0), h1 = __float2half(v1);
                __half h2 = __float2half(v2), h3 = __float2half(v3);
                *(__half2*)(Ch + (size_t)rm * 2048 + cn) = __halves2half2(h0, h1);
                *(__half2*)(Ch + (size_t)(rm + 8) * 2048 + cn) = __halves2half2(h2, h3);
                if (mode == 1) {
                    __half* Cl = P.Cl[z];
                    *(__half2*)(Cl + (size_t)rm * 2048 + cn) =
                        __halves2half2(__float2half(v0 - __half2float(h0)),
                                       __float2half(v1 - __half2float(h1)));
                    *(__half2*)(Cl + (size_t)(rm + 8) * 2048 + cn) =
                        __halves2half2(__float2half(v2 - __half2float(h2)),
                                       __float2half(v3 - __half2float(h3)));
                }
            }
        }
    }
}

// ---------------------------------------------------------------------------
// kv_tc: kvT[bh][e][d] slice = V^T (Qh+Ql) over one seq split, tensor cores.
// ---------------------------------------------------------------------------
#define KV_OQH 0
#define KV_OQL 8192
#define KV_OVH 16384
#define KV_STGB 24576
#define KV_SMEM (3 * KV_STGB)     // 73728

__global__ void __launch_bounds__(256, 2) kv_tc() {
    extern __shared__ char smem[];
    const uint32_t sb = smem_u32(smem);
    const int tid = threadIdx.x;
    const int bh = blockIdx.x;
    const int b = bh >> 4, h = bh & 15;
    const int seq0 = blockIdx.y * (SEQ / SPLITS);   // 1024-chunk
    const int lane = tid & 31, w = tid >> 5;
    const int wm = (w >> 2) * 64;      // e
    const int wn = (w & 3) * 32;       // d
    const int mi = lane >> 3, rowin = lane & 7;

    const int rowA = ((mi >> 1) << 3) + rowin;
    const int rowB = ((mi & 1) << 3) + rowin;
    uint32_t cA[4], cB[2];
#pragma unroll
    for (int mt = 0; mt < 4; mt++)
        cA[mt] = (uint32_t)((((wm + mt * 16 + ((mi & 1) << 3)) >> 3) ^ rowin) << 4);
#pragma unroll
    for (int p = 0; p < 2; p++)
        cB[p] = (uint32_t)((((wn + p * 16 + ((mi >> 1) << 3)) >> 3) ^ rowin) << 4);

    const int lr = tid >> 3, lc = tid & 7;
    const uint32_t dA = (uint32_t)(lr * 256 + ((lc ^ (lr & 7)) << 4));
    const uint32_t dB = (uint32_t)(lr * 256 + (((lc + 8) ^ (lr & 7)) << 4));
    const size_t g0 = (size_t)(b * SEQ + seq0 + lr) * 2048 + h * 128;

    float acc[4][4][4] = {};

#pragma unroll
    for (int s = 0; s < 2; s++) {
        const uint32_t st = sb + s * KV_STGB;
        const size_t go = g0 + (size_t)(s * 32) * 2048;
        CP16(st + KV_OQH + dA, g_qh + go + lc * 8);
        CP16(st + KV_OQH + dB, g_qh + go + (lc + 8) * 8);
        CP16(st + KV_OQL + dA, g_ql + go + lc * 8);
        CP16(st + KV_OQL + dB, g_ql + go + (lc + 8) * 8);
        CP16(st + KV_OVH + dA, g_vh + go + lc * 8);
        CP16(st + KV_OVH + dB, g_vh + go + (lc + 8) * 8);
        CP_COMMIT();
    }

    int cs = 0, ls = 2;
    for (int it = 0; it < 32; it++) {
        CP_WAIT(1);
        __syncthreads();
        const int nx = it + 2;
        if (nx < 32) {
            const uint32_t st2 = sb + ls * KV_STGB;
            const size_t go = g0 + (size_t)(nx * 32) * 2048;
            CP16(st2 + KV_OQH + dA, g_qh + go + lc * 8);
            CP16(st2 + KV_OQH + dB, g_qh + go + (lc + 8) * 8);
            CP16(st2 + KV_OQL + dA, g_ql + go + lc * 8);
            CP16(st2 + KV_OQL + dB, g_ql + go + (lc + 8) * 8);
            CP16(st2 + KV_OVH + dA, g_vh + go + lc * 8);
            CP16(st2 + KV_OVH + dB, g_vh + go + (lc + 8) * 8);
        }
        CP_COMMIT();   // unconditional (tail race fix)
        const uint32_t st = sb + cs * KV_STGB;
#pragma unroll
        for (int ks = 0; ks < 2; ks++) {
            uint32_t av[4][4];
#pragma unroll
            for (int mt = 0; mt < 4; mt++)
                LDMX4T(av[mt], st + KV_OVH + (uint32_t)((ks * 16 + rowA) * 256) + cA[mt]);
            uint32_t bq[2][4];
#pragma unroll
            for (int p = 0; p < 2; p++)
                LDMX4T(bq[p], st + KV_OQH + (uint32_t)((ks * 16 + rowB) * 256) + cB[p]);
#pragma unroll
            for (int mt = 0; mt < 4; mt++)
#pragma unroll
                for (int nt = 0; nt < 4; nt++)
                    MMA_F16(acc[mt][nt], av[mt], bq[nt >> 1][(nt & 1) * 2], bq[nt >> 1][(nt & 1) * 2 + 1]);
#pragma unroll
            for (int p = 0; p < 2; p++)
                LDMX4T(bq[p], st + KV_OQL + (uint32_t)((ks * 16 + rowB) * 256) + cB[p]);
#pragma unroll
            for (int mt = 0; mt < 4; mt++)
#pragma unroll
                for (int nt = 0; nt < 4; nt++)
                    MMA_F16(acc[mt][nt], av[mt], bq[nt >> 1][(nt & 1) * 2], bq[nt >> 1][(nt & 1) * 2 + 1]);
        }
        if (++cs == 3) cs = 0;
        if (++ls == 3) ls = 0;
    }

    float* kvp = g_kv + ((size_t)blockIdx.y * Bn * HEADS + bh) * DHd * DHd;
    const int g = lane >> 2, t = lane & 3;
#pragma unroll
    for (int mt = 0; mt < 4; mt++)
#pragma unroll
        for (int nt = 0; nt < 4; nt++) {
            const int rm = wm + mt * 16 + g;
            const int cn = wn + nt * 8 + 2 * t;
            *(float2*)(kvp + rm * 128 + cn) = make_float2(acc[mt][nt][0], acc[mt][nt][1]);
            *(float2*)(kvp + (rm + 8) * 128 + cn) = make_float2(acc[mt][nt][2], acc[mt][nt][3]);
        }
}

// ---------------------------------------------------------------------------
// kvsum: sum SPLITS fp32 slices -> fp16 hi/lo pair
// ---------------------------------------------------------------------------
__global__ void kvsum_kernel() {
    const int n4 = Bn * HEADS * DHd * DHd / 4;      // 262144
    int i = blockIdx.x * blockDim.x + threadIdx.x;
    if (i >= n4) return;
    const float4* src = (const float4*)g_kv;
    float4 s = src[i];
#pragma unroll
    for (int sp = 1; sp < SPLITS; sp++) {
        float4 t = src[i + (size_t)sp * n4];
        s.x += t.x; s.y += t.y; s.z += t.z; s.w += t.w;
    }
    __half h0 = __float2half(s.x), h1 = __float2half(s.y);
    __half h2 = __float2half(s.z), h3 = __float2half(s.w);
    __half2* dh = (__half2*)g_kvh;
    __half2* dl = (__half2*)g_kvl;
    dh[i * 2 + 0] = __halves2half2(h0, h1);
    dh[i * 2 + 1] = __halves2half2(h2, h3);
    dl[i * 2 + 0] = __halves2half2(__float2half(s.x - __half2float(h0)),
                                   __float2half(s.y - __half2float(h1)));
    dl[i * 2 + 1] = __halves2half2(__float2half(s.z - __half2float(h2)),
                                   __float2half(s.w - __half2float(h3)));
}

// ---------------------------------------------------------------------------
// out_tc: o[m][e] = (Qh+Ql)[m][d] @ (Kh+Kl)T[e][d]  (3-product, drop QlKl).
// Monolithic 128KB smem (qh|ql|kvh|kvl of 32KB), K=128, 8 k-iters. 1 CTA/SM.
// ---------------------------------------------------------------------------
#define OT_OQH 0
#define OT_OQL 32768
#define OT_OKH 65536
#define OT_OKL 98304
#define OT_SMEM 131072

__global__ void __launch_bounds__(256) out_tc() {
    extern __shared__ char smem[];
    const uint32_t sb = smem_u32(smem);
    const int tid = threadIdx.x;
    const int m0 = blockIdx.x * 128;
    const int h = blockIdx.y;
    const int b = m0 >> 12;
    const int lane = tid & 31, w = tid >> 5;
    const int wm = (w >> 2) * 64;
    const int wn = (w & 3) * 32;
    const int mi = lane >> 3, rowin = lane & 7;

#pragma unroll
    for (int i = 0; i < 8; i++) {
        const int widx = tid + i * 256;
        const int row = widx >> 4, c = widx & 15;
        const uint32_t dst = (uint32_t)(row * 256 + ((c ^ (row & 7)) << 4));
        CP16(sb + OT_OQH + dst, g_qh + (size_t)(m0 + row) * 2048 + h * 128 + c * 8);
        CP16(sb + OT_OQL + dst, g_ql + (size_t)(m0 + row) * 2048 + h * 128 + c * 8);
        CP16(sb + OT_OKH + dst, g_kvh + (size_t)(b * HEADS + h) * 16384 + row * 128 + c * 8);
        CP16(sb + OT_OKL + dst, g_kvl + (size_t)(b * HEADS + h) * 16384 + row * 128 + c * 8);
    }
    CP_COMMIT();
    CP_WAIT(0);
    __syncthreads();

    const int arow_ = ((mi & 1) << 3) + rowin;
    const int akc = mi >> 1;
    const int brow_ = ((mi >> 1) << 3) + rowin;
    const int bkc = mi & 1;

    float acc[4][4][4] = {};
#pragma unroll
    for (int kt = 0; kt < 8; kt++) {
        uint32_t bb[2][4];
#pragma unroll
        for (int p = 0; p < 2; p++) {
            const int row = wn + p * 16 + brow_;
            LDMX4(bb[p], sb + OT_OKH + (uint32_t)(row * 256) + (uint32_t)(((kt * 2 + bkc) ^ rowin) << 4));
        }
        uint32_t ahh[4][4];
#pragma unroll
        for (int mt = 0; mt < 4; mt++) {
            const int row = wm + mt * 16 + arow_;
            LDMX4(ahh[mt], sb + OT_OQH + (uint32_t)(row * 256) + (uint32_t)(((kt * 2 + akc) ^ rowin) << 4));
        }
        // Qh * Kh
#pragma unroll
        for (int mt = 0; mt < 4; mt++)
#pragma unroll
            for (int nt = 0; nt < 4; nt++)
                MMA_F16(acc[mt][nt], ahh[mt], bb[nt >> 1][(nt & 1) * 2], bb[nt >> 1][(nt & 1) * 2 + 1]);
        // Ql * Kh
        {
            uint32_t ahl[4][4];
#pragma unroll
            for (int mt = 0; mt < 4; mt++) {
                const int row = wm + mt * 16 + arow_;
                LDMX4(ahl[mt], sb + OT_OQL + (uint32_t)(row * 256) + (uint32_t)(((kt * 2 + akc) ^ rowin) << 4));
            }
#pragma unroll
            for (int mt = 0; mt < 4; mt++)
#pragma unroll
                for (int nt = 0; nt < 4; nt++)
                    MMA_F16(acc[mt][nt], ahl[mt], bb[nt >> 1][(nt & 1) * 2], bb[nt >> 1][(nt & 1) * 2 + 1]);
        }
        // Qh * Kl (reuse bb)
#pragma unroll
        for (int p = 0; p < 2; p++) {
            const int row = wn + p * 16 + brow_;
            LDMX4(bb[p], sb + OT_OKL + (uint32_t)(row * 256) + (uint32_t)(((kt * 2 + bkc) ^ rowin) << 4));
        }
#pragma unroll
        for (int mt = 0; mt < 4; mt++)
#pragma unroll
            for (int nt = 0; nt < 4; nt++)
                MMA_F16(acc[mt][nt], ahh[mt], bb[nt >> 1][(nt & 1) * 2], bb[nt >> 1][(nt & 1) * 2 + 1]);
    }

    const int g = lane >> 2, t = lane & 3;
#pragma unroll
    for (int mt = 0; mt < 4; mt++)
#pragma unroll
        for (int nt = 0; nt < 4; nt++) {
            const int rm = m0 + wm + mt * 16 + g;
            const int cn = h * 128 + wn + nt * 8 + 2 * t;
            *(float2*)(g_o + (size_t)rm * 2048 + cn) = make_float2(acc[mt][nt][0], acc[mt][nt][1]);
            *(float2*)(g_o + (size_t)(rm + 8) * 2048 + cn) = make_float2(acc[mt][nt][2], acc[mt][nt][3]);
        }
}

// ---------------------------------------------------------------------------
// prep kernels
// ---------------------------------------------------------------------------
__global__ void split_kernel(const float* __restrict__ x,
                             __half* __restrict__ h, __half* __restrict__ l, int n4) {
    int i = blockIdx.x * blockDim.x + threadIdx.x;
    if (i >= n4) return;
    float4 v = ((const float4*)x)[i];
    __half h0 = __float2half(v.x), h1 = __float2half(v.y);
    __half h2 = __float2half(v.z), h3 = __float2half(v.w);
    __half2* hp = (__half2*)h;
    __half2* lp = (__half2*)l;
    hp[i * 2 + 0] = __halves2half2(h0, h1);
    hp[i * 2 + 1] = __halves2half2(h2, h3);
    lp[i * 2 + 0] = __halves2half2(__float2half(v.x - __half2float(h0)),
                                   __float2half(v.y - __half2float(h1)));
    lp[i * 2 + 1] = __halves2half2(__float2half(v.z - __half2float(h2)),
                                   __float2half(v.w - __half2float(h3)));
}

struct TsplitBatch {
    const float* W[4];
    __half* T[4];
};
__global__ void tsplit_kernel(TsplitBatch P) {
    __shared__ float tile[32][33];
    const float* __restrict__ W = P.W[blockIdx.z];
    __half* __restrict__ T = P.T[blockIdx.z];
    const int k0 = blockIdx.y * 32, n0 = blockIdx.x * 32;
    const int tx = threadIdx.x, ty = threadIdx.y;
#pragma unroll
    for (int i = 0; i < 32; i += 8)
        tile[ty + i][tx] = W[(size_t)(k0 + ty + i) * 2048 + n0 + tx];
    __syncthreads();
#pragma unroll
    for (int i = 0; i < 32; i += 8)
        T[(size_t)(n0 + ty + i) * 2048 + k0 + tx] = __float2half(tile[tx][ty + i]);
}

// ---------------------------------------------------------------------------
// LayerNorm over HD, * gate u, emit fp16 (hi only — Wo GEMM is 1-product)
// ---------------------------------------------------------------------------
__global__ void ln_mul_kernel(const float* __restrict__ lng, const float* __restrict__ lnb) {
    __shared__ float buf[HD];
    __shared__ float red[256];
    const int row = blockIdx.x;
    const int tid = threadIdx.x;
    const float* orow = g_o + (size_t)row * HD;
    const float* urow = g_u + (size_t)row * HD;

    float s = 0.f;
    for (int c = tid; c < HD; c += 256) { float v = orow[c]; buf[c] = v; s += v; }
    red[tid] = s; __syncthreads();
    for (int off = 128; off; off >>= 1) { if (tid < off) red[tid] += red[tid + off]; __syncthreads(); }
    const float mean = red[0] * (1.f / HD);
    __syncthreads();

    float s2 = 0.f;
    for (int c = tid; c < HD; c += 256) { float d = buf[c] - mean; s2 += d * d; }
    red[tid] = s2; __syncthreads();
    for (int off = 128; off; off >>= 1) { if (tid < off) red[tid] += red[tid + off]; __syncthreads(); }
    const float rstd = rsqrtf(red[0] * (1.f / HD) + 1e-5f);

    for (int c = tid; c < HD; c += 256) {
        float v = ((buf[c] - mean) * rstd * lng[c] + lnb[c]) * urow[c];
        g_lnh[(size_t)row * HD + c] = __float2half(v);
    }
}

// ---------------------------------------------------------------------------
// launch
// ---------------------------------------------------------------------------
extern "C" void kernel_launch(void* const* d_in, const int* in_sizes, int n_in,
                              void* d_out, int out_size) {
    const float* x   = (const float*)d_in[0];
    const float* Wqk = (const float*)d_in[1];
    const float* bqk = (const float*)d_in[2];
    const float* Wv  = (const float*)d_in[3];
    const float* bv  = (const float*)d_in[4];
    const float* Wu  = (const float*)d_in[5];
    const float* bu  = (const float*)d_in[6];
    const float* Wo  = (const float*)d_in[7];
    const float* bo  = (const float*)d_in[8];
    const float* lng = (const float*)d_in[9];
    const float* lnb = (const float*)d_in[10];
    float* out = (float*)d_out;

    float *pu;
    __half *pxh, *pxl, *plnh, *pwqk, *pwv, *pwu, *pwo, *pqh, *pql, *pvh;
    cudaGetSymbolAddress((void**)&pu, g_u);
    cudaGetSymbolAddress((void**)&pxh, g_xh);
    cudaGetSymbolAddress((void**)&pxl, g_xl);
    cudaGetSymbolAddress((void**)&plnh, g_lnh);
    cudaGetSymbolAddress((void**)&pwqk, g_wqk);
    cudaGetSymbolAddress((void**)&pwv, g_wv);
    cudaGetSymbolAddress((void**)&pwu, g_wu);
    cudaGetSymbolAddress((void**)&pwo, g_wo);
    cudaGetSymbolAddress((void**)&pqh, g_qh);
    cudaGetSymbolAddress((void**)&pql, g_ql);
    cudaGetSymbolAddress((void**)&pvh, g_vh);

    cudaFuncSetAttribute(gemm_f16_2p, cudaFuncAttributeMaxDynamicSharedMemorySize, GEMM_SMEM);
    cudaFuncSetAttribute(kv_tc, cudaFuncAttributeMaxDynamicSharedMemorySize, KV_SMEM);
    cudaFuncSetAttribute(out_tc, cudaFuncAttributeMaxDynamicSharedMemorySize, OT_SMEM);

    // prep: split x; transpose 4 weights to fp16 in one launch
    {
        int n4 = MR * Ein / 4;
        split_kernel<<<(n4 + 255) / 256, 256>>>(x, pxh, pxl, n4);
        TsplitBatch T;
        T.W[0] = Wqk; T.T[0] = pwqk;
        T.W[1] = Wv;  T.T[1] = pwv;
        T.W[2] = Wu;  T.T[2] = pwu;
        T.W[3] = Wo;  T.T[3] = pwo;
        tsplit_kernel<<<dim3(64, 64, 4), dim3(32, 8)>>>(T);
    }

    // merged q/v/u GEMM: q(elu, pair, 2-prod), v(silu, half, 1-prod), u(silu, fp32, 1-prod)
    {
        GemmBatch P;
        P.B[0] = pwqk; P.bias[0] = bqk; P.C[0] = nullptr; P.Ch[0] = pqh; P.Cl[0] = pql; P.mode[0] = 1; P.act[0] = 1; P.nprod[0] = 2;
        P.B[1] = pwv;  P.bias[1] = bv;  P.C[1] = nullptr; P.Ch[1] = pvh; P.Cl[1] = nullptr; P.mode[1] = 2; P.act[1] = 2; P.nprod[1] = 1;
        P.B[2] = pwu;  P.bias[2] = bu;  P.C[2] = pu;      P.Ch[2] = nullptr; P.Cl[2] = nullptr; P.mode[2] = 0; P.act[2] = 2; P.nprod[2] = 1;
        dim3 g3(HD / BN, MR / BM, 3);     // (16, 128, 3)
        gemm_f16_2p<<<g3, 256, GEMM_SMEM>>>(pxh, pxl, P);
    }

    // linear attention (tensor cores)
    kv_tc<<<dim3(Bn * HEADS, SPLITS), 256, KV_SMEM>>>();
    kvsum_kernel<<<(Bn * HEADS * DHd * DHd / 4 + 255) / 256, 256>>>();
    out_tc<<<dim3(MR / 128, HEADS), 256, OT_SMEM>>>();

    // LN * gate -> fp16 (hi only)
    ln_mul_kernel<<<MR, 256>>>(lng, lnb);

    // y = ln_out @ Wo + bo (fp32 out, 1-prod: A-lo term ~1.9e-4 dropped)
    {
        GemmBatch P;
        P.B[0] = pwo; P.bias[0] = bo; P.C[0] = out; P.Ch[0] = nullptr; P.Cl[0] = nullptr; P.mode[0] = 0; P.act[0] = 0; P.nprod[0] = 1;
        dim3 g1(HD / BN, MR / BM, 1);
        gemm_f16_2p<<<g1, 256, GEMM_SMEM>>>(plnh, nullptr, P);
    }
}